// round 12
// baseline (speedup 1.0000x reference)
#include <cuda_runtime.h>
#include <math.h>
#include <stdint.h>

#define CB   8
#define PP   2048
#define DKx  256
#define BB   8192
#define TK   4

// output offsets (elements, fp32)
#define OFF_QV   0ULL
#define OFF_QK   67108864ULL
#define OFF_IND  134217728ULL
#define OFF_DIST 134479872ULL
#define OFF_CNT  134742016ULL
#define OFF_FLAT 135004160ULL

#define NSHORT 8

typedef unsigned long long ull;

__device__ int    g_idx[BB * CB * TK];
__device__ int    g_short[BB * CB * NSHORT];
__device__ float  g_knorm[CB * PP];
// transposed keys: coalesced float4 over contraction dim [(c*64 + d4)*2048 + j]
__device__ float4 g_kT[CB * 64 * PP];
// transposed weights for enc (coalesced float4 over contraction dim)
__device__ float4 g_wT_in[64 * 768];       // [d4*768 + col]
__device__ float4 g_wT_out[64 * 256];
__device__ float4 g_wT_f1[64 * 256];
__device__ float4 g_wT_f2[64 * 256];
__device__ float4 g_wT_dec[64 * 256];

// --------------------------------------------------------- packed f32x2 ----
__device__ __forceinline__ ull pack2(float lo, float hi) {
    ull r; asm("mov.b64 %0,{%1,%2};" : "=l"(r) : "f"(lo), "f"(hi)); return r;
}
__device__ __forceinline__ void unpack2(float& lo, float& hi, ull v) {
    asm("mov.b64 {%0,%1},%2;" : "=f"(lo), "=f"(hi) : "l"(v));
}
__device__ __forceinline__ ull fma2(ull a, ull b, ull c) {
    ull d; asm("fma.rn.f32x2 %0,%1,%2,%3;" : "=l"(d) : "l"(a), "l"(b), "l"(c)); return d;
}
__device__ __forceinline__ ull add2(ull a, ull b) {
    ull d; asm("add.rn.f32x2 %0,%1,%2;" : "=l"(d) : "l"(a), "l"(b)); return d;
}
__device__ __forceinline__ ull mul2(ull a, ull b) {
    ull d; asm("mul.rn.f32x2 %0,%1,%2;" : "=l"(d) : "l"(a), "l"(b)); return d;
}

__device__ __forceinline__ float warp_sum(float v) {
    #pragma unroll
    for (int o = 16; o; o >>= 1) v += __shfl_xor_sync(0xffffffffu, v, o);
    return v;
}
__device__ __forceinline__ double warp_sum_d(double v) {
    #pragma unroll
    for (int o = 16; o; o >>= 1) v += __shfl_xor_sync(0xffffffffu, v, o);
    return v;
}

// ------------------------------------------------------------- transposes ---
__global__ void __launch_bounds__(256) transW_kernel(
    const float* __restrict__ src, float4* __restrict__ dst, int NC) {
    int idx = blockIdx.x * 256 + threadIdx.x;           // idx = d4*NC + col
    if (idx >= 64 * NC) return;
    int d4 = idx / NC, col = idx % NC;
    const float* p = src + (size_t)col * 256 + 4 * d4;
    dst[idx] = make_float4(p[0], p[1], p[2], p[3]);
}

__global__ void __launch_bounds__(256) transK_kernel(const float* __restrict__ keys) {
    int idx = blockIdx.x * 256 + threadIdx.x;           // ((c*64+d4)*2048 + j)
    int j = idx & 2047, rest = idx >> 11;
    int d4 = rest & 63, c = rest >> 6;
    const float* p = keys + ((size_t)(c * PP + j)) * 256 + 4 * d4;
    g_kT[idx] = make_float4(p[0], p[1], p[2], p[3]);
}

// -------------------------------------------------------- LN (pair layout) --
// pair layout: buf[d*8 + pair*2 + comp], pair = row>>1, comp = row&1
__device__ __forceinline__ void ln_pair(const float* __restrict__ src,
                                        float* __restrict__ dst,
                                        const float* __restrict__ g,
                                        const float* __restrict__ b, int tid) {
    int w = tid >> 5, lane = tid & 31;
    int off = (w >> 1) * 2 + (w & 1);
    float v[8];
    float s = 0.f;
    #pragma unroll
    for (int k = 0; k < 8; k++) { v[k] = src[(lane + 32 * k) * 8 + off]; s += v[k]; }
    s = warp_sum(s);
    float mu = s * (1.f / 256.f);
    float var = 0.f;
    #pragma unroll
    for (int k = 0; k < 8; k++) { float t = v[k] - mu; var = fmaf(t, t, var); }
    var = warp_sum(var);
    float rs = 1.0f / sqrtf(var * (1.f / 256.f) + 1e-5f);
    #pragma unroll
    for (int k = 0; k < 8; k++) {
        int d = lane + 32 * k;
        dst[d * 8 + off] = (v[k] - mu) * rs * g[d] + b[d];
    }
}

// Packed dot: 4 row-pairs per column; 16-MAC serial chunks, plain chunk sum.
// (Kahan removed: chunked fp32 accumulation ~1e-6 rel, inside the demonstrated
// selection-robustness window from R2/R3; refine guards bin-ties.)
__device__ __forceinline__ void dot8kp(const ulonglong2* __restrict__ Ap,
                                       const float4* __restrict__ wT4, int NC, int col,
                                       ull* out) {
    ull s[4];
    #pragma unroll
    for (int p = 0; p < 4; p++) s[p] = 0ULL;
    #pragma unroll 2
    for (int g = 0; g < 16; ++g) {
        float4 w[4];
        w[0] = __ldg(wT4 + (size_t)(4 * g + 0) * NC + col);
        w[1] = __ldg(wT4 + (size_t)(4 * g + 1) * NC + col);
        w[2] = __ldg(wT4 + (size_t)(4 * g + 2) * NC + col);
        w[3] = __ldg(wT4 + (size_t)(4 * g + 3) * NC + col);
        ull ch0, ch1, ch2, ch3;
        {
            ull wp = pack2(w[0].x, w[0].x);
            ulonglong2 a01 = Ap[(g * 16) * 2 + 0];
            ulonglong2 a23 = Ap[(g * 16) * 2 + 1];
            ch0 = mul2(a01.x, wp); ch1 = mul2(a01.y, wp);
            ch2 = mul2(a23.x, wp); ch3 = mul2(a23.y, wp);
        }
        #pragma unroll
        for (int dd = 1; dd < 16; ++dd) {
            float we = (&w[dd >> 2].x)[dd & 3];
            ull wp = pack2(we, we);
            int d = g * 16 + dd;
            ulonglong2 a01 = Ap[d * 2 + 0];
            ulonglong2 a23 = Ap[d * 2 + 1];
            ch0 = fma2(a01.x, wp, ch0); ch1 = fma2(a01.y, wp, ch1);
            ch2 = fma2(a23.x, wp, ch2); ch3 = fma2(a23.y, wp, ch3);
        }
        s[0] = add2(s[0], ch0); s[1] = add2(s[1], ch1);
        s[2] = add2(s[2], ch2); s[3] = add2(s[3], ch3);
    }
    #pragma unroll
    for (int p = 0; p < 4; p++) out[p] = s[p];
}

// ---------------------------------------------------------------- Kernel A ---
__global__ void __launch_bounds__(256) enc_kernel(
    const float* __restrict__ x,
    const float* __restrict__ ln1_g, const float* __restrict__ ln1_b,
    const float* __restrict__ b_in,  const float* __restrict__ b_out,
    const float* __restrict__ ln2_g, const float* __restrict__ ln2_b,
    const float* __restrict__ fb1,   const float* __restrict__ fb2,
    const float* __restrict__ db,
    float* __restrict__ out_flat)
{
    __shared__ __align__(16) float flatP[256 * 8];   // pair layout residual
    __shared__ __align__(16) float aP[256 * 8];      // pair layout LN/attn-o
    __shared__ __align__(16) float qkv_s[8][768];    // row layout (attention)
    __shared__ float sc[2][8][8];

    float* hP = &qkv_s[0][0];    // ffn hidden (pair layout), aliases dead qkv

    int i = blockIdx.x, tid = threadIdx.x;

    // stage x into pair layout
    for (int idx = tid; idx < 512; idx += 256) {
        int l = idx >> 6, d4 = idx & 63;
        float4 v = *(const float4*)(x + ((size_t)i * 8 + l) * 256 + 4 * d4);
        int off = (l >> 1) * 2 + (l & 1);
        flatP[(4 * d4 + 0) * 8 + off] = v.x;
        flatP[(4 * d4 + 1) * 8 + off] = v.y;
        flatP[(4 * d4 + 2) * 8 + off] = v.z;
        flatP[(4 * d4 + 3) * 8 + off] = v.w;
    }
    __syncthreads();

    ln_pair(flatP, aP, ln1_g, ln1_b, tid);
    __syncthreads();

    // qkv = h0 @ w_in^T + b_in  (row-major out for attention)
    for (int ch = 0; ch < 3; ++ch) {
        int col = ch * 256 + tid;
        ull res[4];
        dot8kp((const ulonglong2*)aP, g_wT_in, 768, col, res);
        float bi = b_in[col];
        #pragma unroll
        for (int p = 0; p < 4; p++) {
            float lo, hi; unpack2(lo, hi, res[p]);
            qkv_s[2 * p][col]     = __fadd_rn(lo, bi);
            qkv_s[2 * p + 1][col] = __fadd_rn(hi, bi);
        }
    }
    __syncthreads();

    // scores (fp32, 4-way split accumulators)
    if (tid < 128) {
        int h = tid >> 6, rem = tid & 63, l = rem >> 3, m = rem & 7;
        const float* q  = &qkv_s[l][h * 128];
        const float* kk = &qkv_s[m][256 + h * 128];
        float a0 = 0.f, a1 = 0.f, a2 = 0.f, a3 = 0.f;
        #pragma unroll 8
        for (int d = 0; d < 128; d += 4) {
            a0 = fmaf(q[d],     kk[d],     a0);
            a1 = fmaf(q[d + 1], kk[d + 1], a1);
            a2 = fmaf(q[d + 2], kk[d + 2], a2);
            a3 = fmaf(q[d + 3], kk[d + 3], a3);
        }
        float s = __fadd_rn(__fadd_rn(a0, a1), __fadd_rn(a2, a3));
        sc[h][l][m] = s / 11.313708498984760f;
    }
    __syncthreads();

    // softmax
    if (tid < 16) {
        int h = tid >> 3, l = tid & 7;
        float* row = sc[h][l];
        float mx = row[0];
        #pragma unroll
        for (int m = 1; m < 8; m++) mx = fmaxf(mx, row[m]);
        float e[8], sm = 0.f;
        #pragma unroll
        for (int m = 0; m < 8; m++) { e[m] = expf(row[m] - mx); sm += e[m]; }
        float inv = 1.f / sm;
        #pragma unroll
        for (int m = 0; m < 8; m++) row[m] = e[m] * inv;
    }
    __syncthreads();

    // o = a @ v -> aP (pair layout)
    {
        int e = tid, h = e >> 7;
        float sl[8];
        #pragma unroll
        for (int l = 0; l < 8; l++) {
            float s = 0.f;
            #pragma unroll
            for (int m = 0; m < 8; m++) s = fmaf(sc[h][l][m], qkv_s[m][512 + e], s);
            sl[l] = s;
        }
        __syncthreads();   // qkv_s reads done before hP alias writes later
        #pragma unroll
        for (int p = 0; p < 4; p++)
            *(ull*)&aP[e * 8 + 2 * p] = pack2(sl[2 * p], sl[2 * p + 1]);
    }
    __syncthreads();

    // proj + residual (pair)
    {
        int col = tid;
        ull res[4];
        dot8kp((const ulonglong2*)aP, g_wT_out, 256, col, res);
        float bo = b_out[col];
        ull bop = pack2(bo, bo);
        #pragma unroll
        for (int p = 0; p < 4; p++) {
            ull old = *(ull*)&flatP[col * 8 + 2 * p];
            *(ull*)&flatP[col * 8 + 2 * p] = add2(add2(res[p], bop), old);
        }
    }
    __syncthreads();

    ln_pair(flatP, aP, ln2_g, ln2_b, tid);
    __syncthreads();

    // ffn1 + gelu -> hP (pair)
    {
        int col = tid;
        ull res[4];
        dot8kp((const ulonglong2*)aP, g_wT_f1, 256, col, res);
        float b1 = fb1[col];
        #pragma unroll
        for (int p = 0; p < 4; p++) {
            float lo, hi; unpack2(lo, hi, res[p]);
            float u0 = __fadd_rn(lo, b1), u1 = __fadd_rn(hi, b1);
            float g0 = 0.5f * u0 * (1.0f + erff(u0 * 0.70710678118654752f));
            float g1 = 0.5f * u1 * (1.0f + erff(u1 * 0.70710678118654752f));
            *(ull*)&hP[col * 8 + 2 * p] = pack2(g0, g1);
        }
    }
    __syncthreads();

    // ffn2 + residual (pair)
    {
        int col = tid;
        ull res[4];
        dot8kp((const ulonglong2*)hP, g_wT_f2, 256, col, res);
        float b2 = fb2[col];
        ull b2p = pack2(b2, b2);
        #pragma unroll
        for (int p = 0; p < 4; p++) {
            ull old = *(ull*)&flatP[col * 8 + 2 * p];
            *(ull*)&flatP[col * 8 + 2 * p] = add2(add2(res[p], b2p), old);
        }
    }
    __syncthreads();

    // dec -> flatten (global, row-major (c,i))
    {
        int col = tid;
        ull res[4];
        dot8kp((const ulonglong2*)flatP, g_wT_dec, 256, col, res);
        float bd = db[col];
        #pragma unroll
        for (int p = 0; p < 4; p++) {
            float lo, hi; unpack2(lo, hi, res[p]);
            out_flat[((size_t)(2 * p) * BB + i) * 256 + col]     = __fadd_rn(lo, bd);
            out_flat[((size_t)(2 * p + 1) * BB + i) * 256 + col] = __fadd_rn(hi, bd);
        }
    }
}

// ---------------------------------------------------------------- knorm ------
__global__ void __launch_bounds__(256) knorm_kernel(const float* __restrict__ keys) {
    int gw = (blockIdx.x * 256 + threadIdx.x) >> 5;
    int lane = threadIdx.x & 31;
    if (gw >= CB * PP) return;
    const float* row = keys + (size_t)gw * 256;
    float s = 0.f;
    #pragma unroll
    for (int k = 0; k < 8; k++) { float t = row[lane + 32 * k]; s = fmaf(t, t, s); }
    s = warp_sum(s);
    if (lane == 0) g_knorm[gw] = s;
}

// ---------------------------------------------------------------- Kernel B ---
// Fused distance GEMM (packed f32x2, 8 row-pairs) + 2-way j blocking + top-8.
__global__ void __launch_bounds__(256) dist_kernel(const float* __restrict__ flat)
{
    __shared__ __align__(16) float Fp[256 * 16];   // pair layout [d][8 pairs]
    __shared__ float S[16][517];
    __shared__ float mv[16][128];
    __shared__ unsigned short mi[16][128];

    int c = blockIdx.y, ib = blockIdx.x, tid = threadIdx.x;
    int i0 = ib * 16;
    int r = tid & 15, sub = tid >> 4;

    for (int idx = tid; idx < 1024; idx += 256) {
        int rr = idx >> 6, d4 = idx & 63;
        float4 v = *(const float4*)(flat + ((size_t)c * BB + i0 + rr) * 256 + d4 * 4);
        int off = (rr >> 1) * 2 + (rr & 1);
        Fp[(4 * d4 + 0) * 16 + off] = v.x;
        Fp[(4 * d4 + 1) * 16 + off] = v.y;
        Fp[(4 * d4 + 2) * 16 + off] = v.z;
        Fp[(4 * d4 + 3) * 16 + off] = v.w;
    }
    __syncthreads();

    float tv[NSHORT];
    int   ti[NSHORT];
    #pragma unroll
    for (int t = 0; t < NSHORT; ++t) { tv[t] = -1e30f; ti[t] = 0; }

    const ulonglong2* Fp2 = (const ulonglong2*)Fp;   // 4 per d

    for (int tile = 0; tile < 4; ++tile) {
        int j = tile * 512 + tid;
        const float4* kp = g_kT + (size_t)c * 64 * PP + j;
        ull acc0[8], acc1[8];
        #pragma unroll
        for (int p = 0; p < 8; ++p) { acc0[p] = 0ULL; acc1[p] = 0ULL; }
        #pragma unroll 2
        for (int d4 = 0; d4 < 64; ++d4) {
            float4 ka = __ldg(kp + (size_t)d4 * PP);
            float4 kb = __ldg(kp + (size_t)d4 * PP + 256);
            #pragma unroll
            for (int e = 0; e < 4; ++e) {
                int d = 4 * d4 + e;
                float kae = (&ka.x)[e], kbe = (&kb.x)[e];
                ull ka2 = pack2(kae, kae);
                ull kb2 = pack2(kbe, kbe);
                ulonglong2 f01 = Fp2[d * 4 + 0];
                ulonglong2 f23 = Fp2[d * 4 + 1];
                ulonglong2 f45 = Fp2[d * 4 + 2];
                ulonglong2 f67 = Fp2[d * 4 + 3];
                acc0[0] = fma2(f01.x, ka2, acc0[0]); acc0[1] = fma2(f01.y, ka2, acc0[1]);
                acc0[2] = fma2(f23.x, ka2, acc0[2]); acc0[3] = fma2(f23.y, ka2, acc0[3]);
                acc0[4] = fma2(f45.x, ka2, acc0[4]); acc0[5] = fma2(f45.y, ka2, acc0[5]);
                acc0[6] = fma2(f67.x, ka2, acc0[6]); acc0[7] = fma2(f67.y, ka2, acc0[7]);
                acc1[0] = fma2(f01.x, kb2, acc1[0]); acc1[1] = fma2(f01.y, kb2, acc1[1]);
                acc1[2] = fma2(f23.x, kb2, acc1[2]); acc1[3] = fma2(f23.y, kb2, acc1[3]);
                acc1[4] = fma2(f45.x, kb2, acc1[4]); acc1[5] = fma2(f45.y, kb2, acc1[5]);
                acc1[6] = fma2(f67.x, kb2, acc1[6]); acc1[7] = fma2(f67.y, kb2, acc1[7]);
            }
        }
        float kn0 = g_knorm[c * PP + j];
        float kn1 = g_knorm[c * PP + j + 256];
        #pragma unroll
        for (int p = 0; p < 8; ++p) {
            float a, b2v;
            unpack2(a, b2v, acc0[p]);
            S[2 * p][tid]     = fmaf(2.f, a,   -kn0);
            S[2 * p + 1][tid] = fmaf(2.f, b2v, -kn0);
            unpack2(a, b2v, acc1[p]);
            S[2 * p][tid + 256]     = fmaf(2.f, a,   -kn1);
            S[2 * p + 1][tid + 256] = fmaf(2.f, b2v, -kn1);
        }
        __syncthreads();
        // per-row top-8 scan: thread (r,sub) scans 32 ascending columns
        #pragma unroll 4
        for (int q = 0; q < 32; ++q) {
            int col = sub * 32 + q;
            float v = S[r][col];
            int jj = tile * 512 + col;
            if (v > tv[NSHORT - 1]) {
                tv[NSHORT - 1] = v; ti[NSHORT - 1] = jj;
                #pragma unroll
                for (int p = NSHORT - 1; p > 0; --p) {
                    if (tv[p] > tv[p - 1] || (tv[p] == tv[p - 1] && ti[p] < ti[p - 1])) {
                        float a = tv[p]; tv[p] = tv[p - 1]; tv[p - 1] = a;
                        int   b = ti[p]; ti[p] = ti[p - 1]; ti[p - 1] = b;
                    }
                }
            }
        }
        __syncthreads();
    }

    // merge 16 per-thread lists per row
    #pragma unroll
    for (int t = 0; t < NSHORT; ++t) {
        mv[r][sub * 8 + t] = tv[t];
        mi[r][sub * 8 + t] = (unsigned short)ti[t];
    }
    __syncthreads();

    if (tid < 16) {
        int row = tid;
        float fv[NSHORT];
        int   fi[NSHORT];
        #pragma unroll
        for (int t = 0; t < NSHORT; ++t) { fv[t] = -1e30f; fi[t] = 0; }
        for (int e = 0; e < 128; ++e) {
            float v = mv[row][e];
            int jj = (int)mi[row][e];
            if (v > fv[NSHORT - 1] || (v == fv[NSHORT - 1] && jj < fi[NSHORT - 1])) {
                fv[NSHORT - 1] = v; fi[NSHORT - 1] = jj;
                #pragma unroll
                for (int p = NSHORT - 1; p > 0; --p) {
                    if (fv[p] > fv[p - 1] || (fv[p] == fv[p - 1] && fi[p] < fi[p - 1])) {
                        float a = fv[p]; fv[p] = fv[p - 1]; fv[p - 1] = a;
                        int   b = fi[p]; fi[p] = fi[p - 1]; fi[p - 1] = b;
                    }
                }
            }
        }
        int ig = i0 + row;
        #pragma unroll
        for (int t = 0; t < NSHORT; ++t)
            g_short[((size_t)ig * 8 + c) * NSHORT + t] = fi[t];
    }
}

// ---------------------------------------------------------------- refine -----
__global__ void __launch_bounds__(256) refine_kernel(
    const float* __restrict__ flat, const float* __restrict__ keys,
    const float* __restrict__ counter, float* __restrict__ out)
{
    int gw = (blockIdx.x * 256 + threadIdx.x) >> 5;   // row = i*8 + c
    int lane = threadIdx.x & 31;
    if (gw >= BB * CB) return;
    int i = gw >> 3, c = gw & 7;

    const float* frow = flat + ((size_t)c * BB + i) * 256;
    double f[8];
    double fn = 0.0;
    #pragma unroll
    for (int k = 0; k < 8; k++) {
        f[k] = (double)frow[lane + 32 * k];
        fn += f[k] * f[k];
    }
    fn = warp_sum_d(fn);

    float sv[NSHORT];
    int   si[NSHORT];
    float A32 = (float)fn;
    #pragma unroll
    for (int t = 0; t < NSHORT; ++t) {
        int idx = g_short[(size_t)gw * NSHORT + t];
        si[t] = idx;
        const float* krow = keys + ((size_t)c * PP + idx) * 256;
        double dot = 0.0, kn = 0.0;
        #pragma unroll
        for (int k = 0; k < 8; k++) {
            double kd = (double)krow[lane + 32 * k];
            dot += f[k] * kd;
            kn  += kd * kd;
        }
        dot = warp_sum_d(dot);
        kn  = warp_sum_d(kn);
        float B32 = 2.0f * (float)dot;
        float C32 = (float)kn;
        float t1  = __fadd_rn(A32, -B32);
        float t2  = __fadd_rn(t1, C32);
        sv[t] = -t2;
    }

    if (lane == 0) {
        #pragma unroll
        for (int a = 0; a < TK; ++a) {
            int best = a;
            #pragma unroll
            for (int b2 = a + 1; b2 < NSHORT; ++b2) {
                if (sv[b2] > sv[best] || (sv[b2] == sv[best] && si[b2] < si[best]))
                    best = b2;
            }
            float vtmp = sv[a]; sv[a] = sv[best]; sv[best] = vtmp;
            int   itmp = si[a]; si[a] = si[best]; si[best] = itmp;
            size_t o = ((size_t)i * 8 + c) * 4 + a;
            out[OFF_IND + o]  = (float)si[a];
            out[OFF_DIST + o] = sv[a];
            out[OFF_CNT + o]  = counter[c * PP + si[a]];
            g_idx[o] = si[a];
        }
    }
}

// ---------------------------------------------------------------- Kernel C ---
__global__ void __launch_bounds__(256) gather_kernel(
    const float* __restrict__ keys, const float* __restrict__ values,
    float* __restrict__ out)
{
    int gw = (blockIdx.x * 256 + threadIdx.x) >> 5;
    int lane = threadIdx.x & 31;
    int c = (gw >> 2) & 7;
    int idx = g_idx[gw];
    const float4* ks = (const float4*)(keys   + ((size_t)c * PP + idx) * 256);
    const float4* vs = (const float4*)(values + ((size_t)c * PP + idx) * 256);
    float4* oqk = (float4*)(out + OFF_QK) + (size_t)gw * 64;
    float4* oqv = (float4*)(out + OFF_QV) + (size_t)gw * 64;
    oqv[lane]      = vs[lane];
    oqv[lane + 32] = vs[lane + 32];
    oqk[lane]      = ks[lane];
    oqk[lane + 32] = ks[lane + 32];
}

// -----------------------------------------------------------------------------
extern "C" void kernel_launch(void* const* d_in, const int* in_sizes, int n_in,
                              void* d_out, int out_size) {
    const float* x       = (const float*)d_in[0];
    const float* keys    = (const float*)d_in[1];
    const float* values  = (const float*)d_in[2];
    const float* counter = (const float*)d_in[3];
    const float* ln1_g   = (const float*)d_in[4];
    const float* ln1_b   = (const float*)d_in[5];
    const float* w_in    = (const float*)d_in[6];
    const float* b_in    = (const float*)d_in[7];
    const float* w_out   = (const float*)d_in[8];
    const float* b_out   = (const float*)d_in[9];
    const float* ln2_g   = (const float*)d_in[10];
    const float* ln2_b   = (const float*)d_in[11];
    const float* fw1     = (const float*)d_in[12];
    const float* fb1     = (const float*)d_in[13];
    const float* fw2     = (const float*)d_in[14];
    const float* fb2     = (const float*)d_in[15];
    const float* dw      = (const float*)d_in[16];
    const float* db      = (const float*)d_in[17];
    float* out = (float*)d_out;

    float4* wt_in;  cudaGetSymbolAddress((void**)&wt_in,  g_wT_in);
    float4* wt_out; cudaGetSymbolAddress((void**)&wt_out, g_wT_out);
    float4* wt_f1;  cudaGetSymbolAddress((void**)&wt_f1,  g_wT_f1);
    float4* wt_f2;  cudaGetSymbolAddress((void**)&wt_f2,  g_wT_f2);
    float4* wt_dec; cudaGetSymbolAddress((void**)&wt_dec, g_wT_dec);

    // launches 1-5 (enc is launch 6 -> captured by ncu -s 5 -c 1)
    transW_kernel<<<(64 * 768 + 255) / 256, 256>>>(w_in,  wt_in,  768);
    transW_kernel<<<(64 * 256 + 255) / 256, 256>>>(w_out, wt_out, 256);
    transW_kernel<<<(64 * 256 + 255) / 256, 256>>>(fw1,   wt_f1,  256);
    transW_kernel<<<(64 * 256 + 255) / 256, 256>>>(fw2,   wt_f2,  256);
    transW_kernel<<<(64 * 256 + 255) / 256, 256>>>(dw,    wt_dec, 256);

    enc_kernel<<<BB, 256>>>(x, ln1_g, ln1_b, b_in, b_out,
                            ln2_g, ln2_b, fb1, fb2, db, out + OFF_FLAT);

    transK_kernel<<<CB * 64 * PP / 256, 256>>>(keys);
    knorm_kernel<<<2048, 256>>>(keys);

    dist_kernel<<<dim3(BB / 16, CB), 256>>>(out + OFF_FLAT);
    refine_kernel<<<BB * CB / 8, 256>>>(out + OFF_FLAT, keys, counter, out);
    gather_kernel<<<32768, 256>>>(keys, values, out);
}

// round 13
// speedup vs baseline: 1.6740x; 1.6740x over previous
#include <cuda_runtime.h>
#include <math.h>
#include <stdint.h>

#define CB   8
#define PP   2048
#define DKx  256
#define BB   8192
#define TK   4

// output offsets (elements, fp32)
#define OFF_QV   0ULL
#define OFF_QK   67108864ULL
#define OFF_IND  134217728ULL
#define OFF_DIST 134479872ULL
#define OFF_CNT  134742016ULL
#define OFF_FLAT 135004160ULL

#define NSHORT 8

typedef unsigned long long ull;

__device__ int    g_idx[BB * CB * TK];
__device__ int    g_short[BB * CB * NSHORT];
__device__ float  g_knorm[CB * PP];
// transposed keys: coalesced float4 over contraction dim [(c*64 + d4)*2048 + j]
__device__ float4 g_kT[CB * 64 * PP];
// transposed weights for enc (coalesced float4 over contraction dim)
__device__ float4 g_wT_in[64 * 768];       // [d4*768 + col]
__device__ float4 g_wT_out[64 * 256];
__device__ float4 g_wT_f1[64 * 256];
__device__ float4 g_wT_f2[64 * 256];
__device__ float4 g_wT_dec[64 * 256];

// --------------------------------------------------------- packed f32x2 ----
__device__ __forceinline__ ull pack2(float lo, float hi) {
    ull r; asm("mov.b64 %0,{%1,%2};" : "=l"(r) : "f"(lo), "f"(hi)); return r;
}
__device__ __forceinline__ void unpack2(float& lo, float& hi, ull v) {
    asm("mov.b64 {%0,%1},%2;" : "=f"(lo), "=f"(hi) : "l"(v));
}
__device__ __forceinline__ ull fma2(ull a, ull b, ull c) {
    ull d; asm("fma.rn.f32x2 %0,%1,%2,%3;" : "=l"(d) : "l"(a), "l"(b), "l"(c)); return d;
}
__device__ __forceinline__ ull add2(ull a, ull b) {
    ull d; asm("add.rn.f32x2 %0,%1,%2;" : "=l"(d) : "l"(a), "l"(b)); return d;
}
__device__ __forceinline__ ull mul2(ull a, ull b) {
    ull d; asm("mul.rn.f32x2 %0,%1,%2;" : "=l"(d) : "l"(a), "l"(b)); return d;
}
// Kahan on packed pairs; fma2(x,-1,y) rounds identically to sub(y,x).
__device__ __forceinline__ void kadd2(ull& s, ull& c, ull v) {
    const ull neg1 = 0xBF800000BF800000ULL;
    ull y = fma2(c, neg1, v);
    ull t = add2(s, y);
    c = fma2(y, neg1, fma2(s, neg1, t));
    s = t;
}

__device__ __forceinline__ float warp_sum(float v) {
    #pragma unroll
    for (int o = 16; o; o >>= 1) v += __shfl_xor_sync(0xffffffffu, v, o);
    return v;
}
__device__ __forceinline__ double warp_sum_d(double v) {
    #pragma unroll
    for (int o = 16; o; o >>= 1) v += __shfl_xor_sync(0xffffffffu, v, o);
    return v;
}

// ------------------------------------------------------------- transposes ---
__global__ void __launch_bounds__(256) transW_kernel(
    const float* __restrict__ src, float4* __restrict__ dst, int NC) {
    int idx = blockIdx.x * 256 + threadIdx.x;           // idx = d4*NC + col
    if (idx >= 64 * NC) return;
    int d4 = idx / NC, col = idx % NC;
    const float* p = src + (size_t)col * 256 + 4 * d4;
    dst[idx] = make_float4(p[0], p[1], p[2], p[3]);
}

__global__ void __launch_bounds__(256) transK_kernel(const float* __restrict__ keys) {
    int idx = blockIdx.x * 256 + threadIdx.x;           // ((c*64+d4)*2048 + j)
    int j = idx & 2047, rest = idx >> 11;
    int d4 = rest & 63, c = rest >> 6;
    const float* p = keys + ((size_t)(c * PP + j)) * 256 + 4 * d4;
    g_kT[idx] = make_float4(p[0], p[1], p[2], p[3]);
}

// Packed compensated dot over 16 rows (8 pairs): identical per-output
// instruction structure to R10's dot8kp (16-MAC serial chunks + kadd2).
__device__ __forceinline__ void dot16kp(const ulonglong2* __restrict__ Ap,
                                        const float4* __restrict__ wT4, int NC, int col,
                                        ull* out) {
    ull s[8], c[8];
    #pragma unroll
    for (int p = 0; p < 8; p++) { s[p] = 0ULL; c[p] = 0ULL; }
    #pragma unroll 2
    for (int g = 0; g < 16; ++g) {
        float4 w[4];
        w[0] = __ldg(wT4 + (size_t)(4 * g + 0) * NC + col);
        w[1] = __ldg(wT4 + (size_t)(4 * g + 1) * NC + col);
        w[2] = __ldg(wT4 + (size_t)(4 * g + 2) * NC + col);
        w[3] = __ldg(wT4 + (size_t)(4 * g + 3) * NC + col);
        ull ch[8];
        {
            ull wp = pack2(w[0].x, w[0].x);
            ulonglong2 a01 = Ap[(g * 16) * 4 + 0];
            ulonglong2 a23 = Ap[(g * 16) * 4 + 1];
            ulonglong2 a45 = Ap[(g * 16) * 4 + 2];
            ulonglong2 a67 = Ap[(g * 16) * 4 + 3];
            ch[0] = mul2(a01.x, wp); ch[1] = mul2(a01.y, wp);
            ch[2] = mul2(a23.x, wp); ch[3] = mul2(a23.y, wp);
            ch[4] = mul2(a45.x, wp); ch[5] = mul2(a45.y, wp);
            ch[6] = mul2(a67.x, wp); ch[7] = mul2(a67.y, wp);
        }
        #pragma unroll
        for (int dd = 1; dd < 16; ++dd) {
            float we = (&w[dd >> 2].x)[dd & 3];
            ull wp = pack2(we, we);
            int d = g * 16 + dd;
            ulonglong2 a01 = Ap[d * 4 + 0];
            ulonglong2 a23 = Ap[d * 4 + 1];
            ulonglong2 a45 = Ap[d * 4 + 2];
            ulonglong2 a67 = Ap[d * 4 + 3];
            ch[0] = fma2(a01.x, wp, ch[0]); ch[1] = fma2(a01.y, wp, ch[1]);
            ch[2] = fma2(a23.x, wp, ch[2]); ch[3] = fma2(a23.y, wp, ch[3]);
            ch[4] = fma2(a45.x, wp, ch[4]); ch[5] = fma2(a45.y, wp, ch[5]);
            ch[6] = fma2(a67.x, wp, ch[6]); ch[7] = fma2(a67.y, wp, ch[7]);
        }
        #pragma unroll
        for (int p = 0; p < 8; p++) kadd2(s[p], c[p], ch[p]);
    }
    #pragma unroll
    for (int p = 0; p < 8; p++) out[p] = add2(s[p], c[p]);
}

// ---------------------------------------------------------------- Kernel A ---
// 2 tokens per CTA: 16 residual rows (token0 c0-7, token1 c0-7), pair layout
// buf[d*16 + row]. Dynamic smem: flatP 16KB | aP 16KB | qkv 48KB | sc 1KB.
__global__ void __launch_bounds__(256, 2) enc_kernel(
    const float* __restrict__ x,
    const float* __restrict__ ln1_g, const float* __restrict__ ln1_b,
    const float* __restrict__ b_in,  const float* __restrict__ b_out,
    const float* __restrict__ ln2_g, const float* __restrict__ ln2_b,
    const float* __restrict__ fb1,   const float* __restrict__ fb2,
    const float* __restrict__ db,
    float* __restrict__ out_flat)
{
    extern __shared__ __align__(16) float smem_dyn[];
    float* flatP = smem_dyn;                 // 4096 floats
    float* aP    = smem_dyn + 4096;          // 4096 floats
    float* qkv   = smem_dyn + 8192;          // 12288 floats [16][768]
    float* sc    = smem_dyn + 20480;         // 256 floats [2][2][8][8]
    float* hP    = qkv;                      // ffn hidden (pair), aliases qkv

    int i0 = blockIdx.x * 2, tid = threadIdx.x;
    int w = tid >> 5, lane = tid & 31;

    // stage x (2 tokens) into pair layout: off == row
    for (int idx = tid; idx < 1024; idx += 256) {
        int l = idx >> 6, d4 = idx & 63;          // l = row 0..15
        int gi = i0 + (l >> 3);
        float4 v = *(const float4*)(x + ((size_t)gi * 8 + (l & 7)) * 256 + 4 * d4);
        flatP[(4 * d4 + 0) * 16 + l] = v.x;
        flatP[(4 * d4 + 1) * 16 + l] = v.y;
        flatP[(4 * d4 + 2) * 16 + l] = v.z;
        flatP[(4 * d4 + 3) * 16 + l] = v.w;
    }
    __syncthreads();

    // LN1: each warp handles rows w and w+8
    #pragma unroll
    for (int rr = w; rr < 16; rr += 8) {
        float v[8];
        float s = 0.f;
        #pragma unroll
        for (int k = 0; k < 8; k++) { v[k] = flatP[(lane + 32 * k) * 16 + rr]; s += v[k]; }
        s = warp_sum(s);
        float mu = s * (1.f / 256.f);
        float var = 0.f;
        #pragma unroll
        for (int k = 0; k < 8; k++) { float t = v[k] - mu; var = fmaf(t, t, var); }
        var = warp_sum(var);
        float rs = 1.0f / sqrtf(var * (1.f / 256.f) + 1e-5f);
        #pragma unroll
        for (int k = 0; k < 8; k++) {
            int d = lane + 32 * k;
            aP[d * 16 + rr] = (v[k] - mu) * rs * ln1_g[d] + ln1_b[d];
        }
    }
    __syncthreads();

    // qkv = h0 @ w_in^T + b_in  (row-major out for attention)
    for (int ch = 0; ch < 3; ++ch) {
        int col = ch * 256 + tid;
        ull res[8];
        dot16kp((const ulonglong2*)aP, g_wT_in, 768, col, res);
        float bi = b_in[col];
        #pragma unroll
        for (int p = 0; p < 8; p++) {
            float lo, hi; unpack2(lo, hi, res[p]);
            qkv[(2 * p) * 768 + col]     = __fadd_rn(lo, bi);
            qkv[(2 * p + 1) * 768 + col] = __fadd_rn(hi, bi);
        }
    }
    __syncthreads();

    // scores: 2 tokens x 2 heads x 64 (l,m) = 256 threads
    {
        int t = tid >> 7, h = (tid >> 6) & 1, rem = tid & 63, l = rem >> 3, m = rem & 7;
        const float* q  = &qkv[(t * 8 + l) * 768 + h * 128];
        const float* kk = &qkv[(t * 8 + m) * 768 + 256 + h * 128];
        float a0 = 0.f, a1 = 0.f, a2 = 0.f, a3 = 0.f;
        #pragma unroll 8
        for (int d = 0; d < 128; d += 4) {
            a0 = fmaf(q[d],     kk[d],     a0);
            a1 = fmaf(q[d + 1], kk[d + 1], a1);
            a2 = fmaf(q[d + 2], kk[d + 2], a2);
            a3 = fmaf(q[d + 3], kk[d + 3], a3);
        }
        float s = __fadd_rn(__fadd_rn(a0, a1), __fadd_rn(a2, a3));
        sc[((t * 2 + h) * 8 + l) * 8 + m] = s / 11.313708498984760f;
    }
    __syncthreads();

    // softmax over m: 32 rows (2 tokens x 2 heads x 8 l)
    if (tid < 32) {
        float* row = &sc[tid * 8];
        float mx = row[0];
        #pragma unroll
        for (int m = 1; m < 8; m++) mx = fmaxf(mx, row[m]);
        float e[8], sm = 0.f;
        #pragma unroll
        for (int m = 0; m < 8; m++) { e[m] = expf(row[m] - mx); sm += e[m]; }
        float inv = 1.f / sm;
        #pragma unroll
        for (int m = 0; m < 8; m++) row[m] = e[m] * inv;
    }
    __syncthreads();

    // o = a @ v -> aP (pair layout, 16 rows)
    {
        int e = tid, h = e >> 7;
        float sl[16];
        #pragma unroll
        for (int t = 0; t < 2; t++) {
            #pragma unroll
            for (int l = 0; l < 8; l++) {
                float s = 0.f;
                #pragma unroll
                for (int m = 0; m < 8; m++)
                    s = fmaf(sc[((t * 2 + h) * 8 + l) * 8 + m],
                             qkv[(t * 8 + m) * 768 + 512 + e], s);
                sl[t * 8 + l] = s;
            }
        }
        __syncthreads();   // aP reads (qkv GEMM) + qkv reads done
        #pragma unroll
        for (int p = 0; p < 8; p++)
            *(ull*)&aP[e * 16 + 2 * p] = pack2(sl[2 * p], sl[2 * p + 1]);
    }
    __syncthreads();

    // proj + residual (pair)
    {
        int col = tid;
        ull res[8];
        dot16kp((const ulonglong2*)aP, g_wT_out, 256, col, res);
        float bo = b_out[col];
        ull bop = pack2(bo, bo);
        #pragma unroll
        for (int p = 0; p < 8; p++) {
            ull old = *(ull*)&flatP[col * 16 + 2 * p];
            *(ull*)&flatP[col * 16 + 2 * p] = add2(add2(res[p], bop), old);
        }
    }
    __syncthreads();

    // LN2
    #pragma unroll
    for (int rr = w; rr < 16; rr += 8) {
        float v[8];
        float s = 0.f;
        #pragma unroll
        for (int k = 0; k < 8; k++) { v[k] = flatP[(lane + 32 * k) * 16 + rr]; s += v[k]; }
        s = warp_sum(s);
        float mu = s * (1.f / 256.f);
        float var = 0.f;
        #pragma unroll
        for (int k = 0; k < 8; k++) { float t = v[k] - mu; var = fmaf(t, t, var); }
        var = warp_sum(var);
        float rs = 1.0f / sqrtf(var * (1.f / 256.f) + 1e-5f);
        #pragma unroll
        for (int k = 0; k < 8; k++) {
            int d = lane + 32 * k;
            aP[d * 16 + rr] = (v[k] - mu) * rs * ln2_g[d] + ln2_b[d];
        }
    }
    __syncthreads();

    // ffn1 + gelu -> hP (pair; aliases qkv, which is dead now)
    {
        int col = tid;
        ull res[8];
        dot16kp((const ulonglong2*)aP, g_wT_f1, 256, col, res);
        float b1 = fb1[col];
        #pragma unroll
        for (int p = 0; p < 8; p++) {
            float lo, hi; unpack2(lo, hi, res[p]);
            float u0 = __fadd_rn(lo, b1), u1 = __fadd_rn(hi, b1);
            float g0 = 0.5f * u0 * (1.0f + erff(u0 * 0.70710678118654752f));
            float g1 = 0.5f * u1 * (1.0f + erff(u1 * 0.70710678118654752f));
            *(ull*)&hP[col * 16 + 2 * p] = pack2(g0, g1);
        }
    }
    __syncthreads();

    // ffn2 + residual (pair)
    {
        int col = tid;
        ull res[8];
        dot16kp((const ulonglong2*)hP, g_wT_f2, 256, col, res);
        float b2 = fb2[col];
        ull b2p = pack2(b2, b2);
        #pragma unroll
        for (int p = 0; p < 8; p++) {
            ull old = *(ull*)&flatP[col * 16 + 2 * p];
            *(ull*)&flatP[col * 16 + 2 * p] = add2(add2(res[p], b2p), old);
        }
    }
    __syncthreads();

    // dec -> flatten (global, row-major (c,i))
    {
        int col = tid;
        ull res[8];
        dot16kp((const ulonglong2*)flatP, g_wT_dec, 256, col, res);
        float bd = db[col];
        #pragma unroll
        for (int p = 0; p < 8; p++) {
            float lo, hi; unpack2(lo, hi, res[p]);
            int gi = i0 + (p >> 2);
            int c0 = (2 * p) & 7, c1 = (2 * p + 1) & 7;
            out_flat[((size_t)c0 * BB + gi) * 256 + col] = __fadd_rn(lo, bd);
            out_flat[((size_t)c1 * BB + gi) * 256 + col] = __fadd_rn(hi, bd);
        }
    }
}

// ---------------------------------------------------------------- knorm ------
__global__ void __launch_bounds__(256) knorm_kernel(const float* __restrict__ keys) {
    int gw = (blockIdx.x * 256 + threadIdx.x) >> 5;
    int lane = threadIdx.x & 31;
    if (gw >= CB * PP) return;
    const float* row = keys + (size_t)gw * 256;
    float s = 0.f;
    #pragma unroll
    for (int k = 0; k < 8; k++) { float t = row[lane + 32 * k]; s = fmaf(t, t, s); }
    s = warp_sum(s);
    if (lane == 0) g_knorm[gw] = s;
}

// ---------------------------------------------------------------- Kernel B ---
// Fused distance GEMM (packed f32x2, 8 row-pairs) + 2-way j blocking + top-8.
// (exact R10 champion code)
__global__ void __launch_bounds__(256) dist_kernel(const float* __restrict__ flat)
{
    __shared__ __align__(16) float Fp[256 * 16];   // pair layout [d][8 pairs]
    __shared__ float S[16][517];
    __shared__ float mv[16][128];
    __shared__ unsigned short mi[16][128];

    int c = blockIdx.y, ib = blockIdx.x, tid = threadIdx.x;
    int i0 = ib * 16;
    int r = tid & 15, sub = tid >> 4;

    for (int idx = tid; idx < 1024; idx += 256) {
        int rr = idx >> 6, d4 = idx & 63;
        float4 v = *(const float4*)(flat + ((size_t)c * BB + i0 + rr) * 256 + d4 * 4);
        int off = (rr >> 1) * 2 + (rr & 1);
        Fp[(4 * d4 + 0) * 16 + off] = v.x;
        Fp[(4 * d4 + 1) * 16 + off] = v.y;
        Fp[(4 * d4 + 2) * 16 + off] = v.z;
        Fp[(4 * d4 + 3) * 16 + off] = v.w;
    }
    __syncthreads();

    float tv[NSHORT];
    int   ti[NSHORT];
    #pragma unroll
    for (int t = 0; t < NSHORT; ++t) { tv[t] = -1e30f; ti[t] = 0; }

    const ulonglong2* Fp2 = (const ulonglong2*)Fp;   // 4 per d

    for (int tile = 0; tile < 4; ++tile) {
        int j = tile * 512 + tid;
        const float4* kp = g_kT + (size_t)c * 64 * PP + j;
        ull acc0[8], acc1[8];
        #pragma unroll
        for (int p = 0; p < 8; ++p) { acc0[p] = 0ULL; acc1[p] = 0ULL; }
        #pragma unroll 2
        for (int d4 = 0; d4 < 64; ++d4) {
            float4 ka = __ldg(kp + (size_t)d4 * PP);
            float4 kb = __ldg(kp + (size_t)d4 * PP + 256);
            #pragma unroll
            for (int e = 0; e < 4; ++e) {
                int d = 4 * d4 + e;
                float kae = (&ka.x)[e], kbe = (&kb.x)[e];
                ull ka2 = pack2(kae, kae);
                ull kb2 = pack2(kbe, kbe);
                ulonglong2 f01 = Fp2[d * 4 + 0];
                ulonglong2 f23 = Fp2[d * 4 + 1];
                ulonglong2 f45 = Fp2[d * 4 + 2];
                ulonglong2 f67 = Fp2[d * 4 + 3];
                acc0[0] = fma2(f01.x, ka2, acc0[0]); acc0[1] = fma2(f01.y, ka2, acc0[1]);
                acc0[2] = fma2(f23.x, ka2, acc0[2]); acc0[3] = fma2(f23.y, ka2, acc0[3]);
                acc0[4] = fma2(f45.x, ka2, acc0[4]); acc0[5] = fma2(f45.y, ka2, acc0[5]);
                acc0[6] = fma2(f67.x, ka2, acc0[6]); acc0[7] = fma2(f67.y, ka2, acc0[7]);
                acc1[0] = fma2(f01.x, kb2, acc1[0]); acc1[1] = fma2(f01.y, kb2, acc1[1]);
                acc1[2] = fma2(f23.x, kb2, acc1[2]); acc1[3] = fma2(f23.y, kb2, acc1[3]);
                acc1[4] = fma2(f45.x, kb2, acc1[4]); acc1[5] = fma2(f45.y, kb2, acc1[5]);
                acc1[6] = fma2(f67.x, kb2, acc1[6]); acc1[7] = fma2(f67.y, kb2, acc1[7]);
            }
        }
        float kn0 = g_knorm[c * PP + j];
        float kn1 = g_knorm[c * PP + j + 256];
        #pragma unroll
        for (int p = 0; p < 8; ++p) {
            float a, b2v;
            unpack2(a, b2v, acc0[p]);
            S[2 * p][tid]     = fmaf(2.f, a,   -kn0);
            S[2 * p + 1][tid] = fmaf(2.f, b2v, -kn0);
            unpack2(a, b2v, acc1[p]);
            S[2 * p][tid + 256]     = fmaf(2.f, a,   -kn1);
            S[2 * p + 1][tid + 256] = fmaf(2.f, b2v, -kn1);
        }
        __syncthreads();
        // per-row top-8 scan: thread (r,sub) scans 32 ascending columns
        #pragma unroll 4
        for (int q = 0; q < 32; ++q) {
            int col = sub * 32 + q;
            float v = S[r][col];
            int jj = tile * 512 + col;
            if (v > tv[NSHORT - 1]) {
                tv[NSHORT - 1] = v; ti[NSHORT - 1] = jj;
                #pragma unroll
                for (int p = NSHORT - 1; p > 0; --p) {
                    if (tv[p] > tv[p - 1] || (tv[p] == tv[p - 1] && ti[p] < ti[p - 1])) {
                        float a = tv[p]; tv[p] = tv[p - 1]; tv[p - 1] = a;
                        int   b = ti[p]; ti[p] = ti[p - 1]; ti[p - 1] = b;
                    }
                }
            }
        }
        __syncthreads();
    }

    // merge 16 per-thread lists per row
    #pragma unroll
    for (int t = 0; t < NSHORT; ++t) {
        mv[r][sub * 8 + t] = tv[t];
        mi[r][sub * 8 + t] = (unsigned short)ti[t];
    }
    __syncthreads();

    if (tid < 16) {
        int row = tid;
        float fv[NSHORT];
        int   fi[NSHORT];
        #pragma unroll
        for (int t = 0; t < NSHORT; ++t) { fv[t] = -1e30f; fi[t] = 0; }
        for (int e = 0; e < 128; ++e) {
            float v = mv[row][e];
            int jj = (int)mi[row][e];
            if (v > fv[NSHORT - 1] || (v == fv[NSHORT - 1] && jj < fi[NSHORT - 1])) {
                fv[NSHORT - 1] = v; fi[NSHORT - 1] = jj;
                #pragma unroll
                for (int p = NSHORT - 1; p > 0; --p) {
                    if (fv[p] > fv[p - 1] || (fv[p] == fv[p - 1] && fi[p] < fi[p - 1])) {
                        float a = fv[p]; fv[p] = fv[p - 1]; fv[p - 1] = a;
                        int   b = fi[p]; fi[p] = fi[p - 1]; fi[p - 1] = b;
                    }
                }
            }
        }
        int ig = i0 + row;
        #pragma unroll
        for (int t = 0; t < NSHORT; ++t)
            g_short[((size_t)ig * 8 + c) * NSHORT + t] = fi[t];
    }
}

// ---------------------------------------------------------------- refine -----
__global__ void __launch_bounds__(256) refine_kernel(
    const float* __restrict__ flat, const float* __restrict__ keys,
    const float* __restrict__ counter, float* __restrict__ out)
{
    int gw = (blockIdx.x * 256 + threadIdx.x) >> 5;   // row = i*8 + c
    int lane = threadIdx.x & 31;
    if (gw >= BB * CB) return;
    int i = gw >> 3, c = gw & 7;

    const float* frow = flat + ((size_t)c * BB + i) * 256;
    double f[8];
    double fn = 0.0;
    #pragma unroll
    for (int k = 0; k < 8; k++) {
        f[k] = (double)frow[lane + 32 * k];
        fn += f[k] * f[k];
    }
    fn = warp_sum_d(fn);

    float sv[NSHORT];
    int   si[NSHORT];
    float A32 = (float)fn;
    #pragma unroll
    for (int t = 0; t < NSHORT; ++t) {
        int idx = g_short[(size_t)gw * NSHORT + t];
        si[t] = idx;
        const float* krow = keys + ((size_t)c * PP + idx) * 256;
        double dot = 0.0, kn = 0.0;
        #pragma unroll
        for (int k = 0; k < 8; k++) {
            double kd = (double)krow[lane + 32 * k];
            dot += f[k] * kd;
            kn  += kd * kd;
        }
        dot = warp_sum_d(dot);
        kn  = warp_sum_d(kn);
        float B32 = 2.0f * (float)dot;
        float C32 = (float)kn;
        float t1  = __fadd_rn(A32, -B32);
        float t2  = __fadd_rn(t1, C32);
        sv[t] = -t2;
    }

    if (lane == 0) {
        #pragma unroll
        for (int a = 0; a < TK; ++a) {
            int best = a;
            #pragma unroll
            for (int b2 = a + 1; b2 < NSHORT; ++b2) {
                if (sv[b2] > sv[best] || (sv[b2] == sv[best] && si[b2] < si[best]))
                    best = b2;
            }
            float vtmp = sv[a]; sv[a] = sv[best]; sv[best] = vtmp;
            int   itmp = si[a]; si[a] = si[best]; si[best] = itmp;
            size_t o = ((size_t)i * 8 + c) * 4 + a;
            out[OFF_IND + o]  = (float)si[a];
            out[OFF_DIST + o] = sv[a];
            out[OFF_CNT + o]  = counter[c * PP + si[a]];
            g_idx[o] = si[a];
        }
    }
}

// ---------------------------------------------------------------- Kernel C ---
__global__ void __launch_bounds__(256) gather_kernel(
    const float* __restrict__ keys, const float* __restrict__ values,
    float* __restrict__ out)
{
    int gw = (blockIdx.x * 256 + threadIdx.x) >> 5;
    int lane = threadIdx.x & 31;
    int c = (gw >> 2) & 7;
    int idx = g_idx[gw];
    const float4* ks = (const float4*)(keys   + ((size_t)c * PP + idx) * 256);
    const float4* vs = (const float4*)(values + ((size_t)c * PP + idx) * 256);
    float4* oqk = (float4*)(out + OFF_QK) + (size_t)gw * 64;
    float4* oqv = (float4*)(out + OFF_QV) + (size_t)gw * 64;
    oqv[lane]      = vs[lane];
    oqv[lane + 32] = vs[lane + 32];
    oqk[lane]      = ks[lane];
    oqk[lane + 32] = ks[lane + 32];
}

// -----------------------------------------------------------------------------
#define ENC_SMEM 82944

extern "C" void kernel_launch(void* const* d_in, const int* in_sizes, int n_in,
                              void* d_out, int out_size) {
    const float* x       = (const float*)d_in[0];
    const float* keys    = (const float*)d_in[1];
    const float* values  = (const float*)d_in[2];
    const float* counter = (const float*)d_in[3];
    const float* ln1_g   = (const float*)d_in[4];
    const float* ln1_b   = (const float*)d_in[5];
    const float* w_in    = (const float*)d_in[6];
    const float* b_in    = (const float*)d_in[7];
    const float* w_out   = (const float*)d_in[8];
    const float* b_out   = (const float*)d_in[9];
    const float* ln2_g   = (const float*)d_in[10];
    const float* ln2_b   = (const float*)d_in[11];
    const float* fw1     = (const float*)d_in[12];
    const float* fb1     = (const float*)d_in[13];
    const float* fw2     = (const float*)d_in[14];
    const float* fb2     = (const float*)d_in[15];
    const float* dw      = (const float*)d_in[16];
    const float* db      = (const float*)d_in[17];
    float* out = (float*)d_out;

    cudaFuncSetAttribute(enc_kernel,
                         cudaFuncAttributeMaxDynamicSharedMemorySize, ENC_SMEM);

    float4* wt_in;  cudaGetSymbolAddress((void**)&wt_in,  g_wT_in);
    float4* wt_out; cudaGetSymbolAddress((void**)&wt_out, g_wT_out);
    float4* wt_f1;  cudaGetSymbolAddress((void**)&wt_f1,  g_wT_f1);
    float4* wt_f2;  cudaGetSymbolAddress((void**)&wt_f2,  g_wT_f2);
    float4* wt_dec; cudaGetSymbolAddress((void**)&wt_dec, g_wT_dec);

    transW_kernel<<<(64 * 768 + 255) / 256, 256>>>(w_in,  wt_in,  768);
    transW_kernel<<<(64 * 256 + 255) / 256, 256>>>(w_out, wt_out, 256);
    transW_kernel<<<(64 * 256 + 255) / 256, 256>>>(fw1,   wt_f1,  256);
    transW_kernel<<<(64 * 256 + 255) / 256, 256>>>(fw2,   wt_f2,  256);
    transW_kernel<<<(64 * 256 + 255) / 256, 256>>>(dw,    wt_dec, 256);

    enc_kernel<<<BB / 2, 256, ENC_SMEM>>>(x, ln1_g, ln1_b, b_in, b_out,
                                          ln2_g, ln2_b, fb1, fb2, db,
                                          out + OFF_FLAT);

    transK_kernel<<<CB * 64 * PP / 256, 256>>>(keys);
    knorm_kernel<<<2048, 256>>>(keys);

    dist_kernel<<<dim3(BB / 16, CB), 256>>>(out + OFF_FLAT);
    refine_kernel<<<BB * CB / 8, 256>>>(out + OFF_FLAT, keys, counter, out);
    gather_kernel<<<32768, 256>>>(keys, values, out);
}

// round 14
// speedup vs baseline: 1.8165x; 1.0851x over previous
#include <cuda_runtime.h>
#include <math.h>
#include <stdint.h>

#define CB   8
#define PP   2048
#define DKx  256
#define BB   8192
#define TK   4

// output offsets (elements, fp32)
#define OFF_QV   0ULL
#define OFF_QK   67108864ULL
#define OFF_IND  134217728ULL
#define OFF_DIST 134479872ULL
#define OFF_CNT  134742016ULL
#define OFF_FLAT 135004160ULL

#define NSHORT 8

typedef unsigned long long ull;

__device__ int    g_idx[BB * CB * TK];
__device__ int    g_short[BB * CB * NSHORT];
__device__ float  g_knorm[CB * PP];     // fp64-accumulated, fp32-rounded |k|^2
// transposed keys: coalesced float4 over contraction dim [(c*64 + d4)*2048 + j]
__device__ float4 g_kT[CB * 64 * PP];
// transposed weights for enc (coalesced float4 over contraction dim)
__device__ float4 g_wT_in[64 * 768];       // [d4*768 + col]
__device__ float4 g_wT_out[64 * 256];
__device__ float4 g_wT_f1[64 * 256];
__device__ float4 g_wT_f2[64 * 256];
__device__ float4 g_wT_dec[64 * 256];

// --------------------------------------------------------- packed f32x2 ----
__device__ __forceinline__ ull pack2(float lo, float hi) {
    ull r; asm("mov.b64 %0,{%1,%2};" : "=l"(r) : "f"(lo), "f"(hi)); return r;
}
__device__ __forceinline__ void unpack2(float& lo, float& hi, ull v) {
    asm("mov.b64 {%0,%1},%2;" : "=f"(lo), "=f"(hi) : "l"(v));
}
__device__ __forceinline__ ull fma2(ull a, ull b, ull c) {
    ull d; asm("fma.rn.f32x2 %0,%1,%2,%3;" : "=l"(d) : "l"(a), "l"(b), "l"(c)); return d;
}
__device__ __forceinline__ ull add2(ull a, ull b) {
    ull d; asm("add.rn.f32x2 %0,%1,%2;" : "=l"(d) : "l"(a), "l"(b)); return d;
}
__device__ __forceinline__ ull mul2(ull a, ull b) {
    ull d; asm("mul.rn.f32x2 %0,%1,%2;" : "=l"(d) : "l"(a), "l"(b)); return d;
}
// Kahan on packed pairs; fma2(x,-1,y) rounds identically to sub(y,x).
__device__ __forceinline__ void kadd2(ull& s, ull& c, ull v) {
    const ull neg1 = 0xBF800000BF800000ULL;
    ull y = fma2(c, neg1, v);
    ull t = add2(s, y);
    c = fma2(y, neg1, fma2(s, neg1, t));
    s = t;
}

__device__ __forceinline__ float warp_sum(float v) {
    #pragma unroll
    for (int o = 16; o; o >>= 1) v += __shfl_xor_sync(0xffffffffu, v, o);
    return v;
}
__device__ __forceinline__ double warp_sum_d(double v) {
    #pragma unroll
    for (int o = 16; o; o >>= 1) v += __shfl_xor_sync(0xffffffffu, v, o);
    return v;
}

// ------------------------------------------------------------- transposes ---
__global__ void __launch_bounds__(256) transW_kernel(
    const float* __restrict__ src, float4* __restrict__ dst, int NC) {
    int idx = blockIdx.x * 256 + threadIdx.x;           // idx = d4*NC + col
    if (idx >= 64 * NC) return;
    int d4 = idx / NC, col = idx % NC;
    const float* p = src + (size_t)col * 256 + 4 * d4;
    dst[idx] = make_float4(p[0], p[1], p[2], p[3]);
}

__global__ void __launch_bounds__(256) transK_kernel(const float* __restrict__ keys) {
    int idx = blockIdx.x * 256 + threadIdx.x;           // ((c*64+d4)*2048 + j)
    int j = idx & 2047, rest = idx >> 11;
    int d4 = rest & 63, c = rest >> 6;
    const float* p = keys + ((size_t)(c * PP + j)) * 256 + 4 * d4;
    g_kT[idx] = make_float4(p[0], p[1], p[2], p[3]);
}

// Packed compensated dot over 16 rows (8 pairs): 32-MAC serial chunks + kadd2.
__device__ __forceinline__ void dot16kp(const ulonglong2* __restrict__ Ap,
                                        const float4* __restrict__ wT4, int NC, int col,
                                        ull* out) {
    ull s[8], c[8];
    #pragma unroll
    for (int p = 0; p < 8; p++) { s[p] = 0ULL; c[p] = 0ULL; }
    #pragma unroll 2
    for (int g = 0; g < 8; ++g) {
        float4 w[8];
        #pragma unroll
        for (int q = 0; q < 8; ++q)
            w[q] = __ldg(wT4 + (size_t)(8 * g + q) * NC + col);
        ull ch[8];
        {
            ull wp = pack2(w[0].x, w[0].x);
            ulonglong2 a01 = Ap[(g * 32) * 4 + 0];
            ulonglong2 a23 = Ap[(g * 32) * 4 + 1];
            ulonglong2 a45 = Ap[(g * 32) * 4 + 2];
            ulonglong2 a67 = Ap[(g * 32) * 4 + 3];
            ch[0] = mul2(a01.x, wp); ch[1] = mul2(a01.y, wp);
            ch[2] = mul2(a23.x, wp); ch[3] = mul2(a23.y, wp);
            ch[4] = mul2(a45.x, wp); ch[5] = mul2(a45.y, wp);
            ch[6] = mul2(a67.x, wp); ch[7] = mul2(a67.y, wp);
        }
        #pragma unroll
        for (int dd = 1; dd < 32; ++dd) {
            float we = (&w[dd >> 2].x)[dd & 3];
            ull wp = pack2(we, we);
            int d = g * 32 + dd;
            ulonglong2 a01 = Ap[d * 4 + 0];
            ulonglong2 a23 = Ap[d * 4 + 1];
            ulonglong2 a45 = Ap[d * 4 + 2];
            ulonglong2 a67 = Ap[d * 4 + 3];
            ch[0] = fma2(a01.x, wp, ch[0]); ch[1] = fma2(a01.y, wp, ch[1]);
            ch[2] = fma2(a23.x, wp, ch[2]); ch[3] = fma2(a23.y, wp, ch[3]);
            ch[4] = fma2(a45.x, wp, ch[4]); ch[5] = fma2(a45.y, wp, ch[5]);
            ch[6] = fma2(a67.x, wp, ch[6]); ch[7] = fma2(a67.y, wp, ch[7]);
        }
        #pragma unroll
        for (int p = 0; p < 8; p++) kadd2(s[p], c[p], ch[p]);
    }
    #pragma unroll
    for (int p = 0; p < 8; p++) out[p] = add2(s[p], c[p]);
}

// ---------------------------------------------------------------- Kernel A ---
// 2 tokens per CTA: 16 residual rows (token0 c0-7, token1 c0-7), pair layout
// buf[d*16 + row]. Dynamic smem: flatP 16KB | aP 16KB | qkv 48KB | sc 1KB.
__global__ void __launch_bounds__(256, 2) enc_kernel(
    const float* __restrict__ x,
    const float* __restrict__ ln1_g, const float* __restrict__ ln1_b,
    const float* __restrict__ b_in,  const float* __restrict__ b_out,
    const float* __restrict__ ln2_g, const float* __restrict__ ln2_b,
    const float* __restrict__ fb1,   const float* __restrict__ fb2,
    const float* __restrict__ db,
    float* __restrict__ out_flat)
{
    extern __shared__ __align__(16) float smem_dyn[];
    float* flatP = smem_dyn;                 // 4096 floats
    float* aP    = smem_dyn + 4096;          // 4096 floats
    float* qkv   = smem_dyn + 8192;          // 12288 floats [16][768]
    float* sc    = smem_dyn + 20480;         // 256 floats [2][2][8][8]
    float* hP    = qkv;                      // ffn hidden (pair), aliases qkv

    int i0 = blockIdx.x * 2, tid = threadIdx.x;
    int w = tid >> 5, lane = tid & 31;

    // stage x (2 tokens) into pair layout: off == row
    for (int idx = tid; idx < 1024; idx += 256) {
        int l = idx >> 6, d4 = idx & 63;          // l = row 0..15
        int gi = i0 + (l >> 3);
        float4 v = *(const float4*)(x + ((size_t)gi * 8 + (l & 7)) * 256 + 4 * d4);
        flatP[(4 * d4 + 0) * 16 + l] = v.x;
        flatP[(4 * d4 + 1) * 16 + l] = v.y;
        flatP[(4 * d4 + 2) * 16 + l] = v.z;
        flatP[(4 * d4 + 3) * 16 + l] = v.w;
    }
    __syncthreads();

    // LN1: each warp handles rows w and w+8
    #pragma unroll
    for (int rr = w; rr < 16; rr += 8) {
        float v[8];
        float s = 0.f;
        #pragma unroll
        for (int k = 0; k < 8; k++) { v[k] = flatP[(lane + 32 * k) * 16 + rr]; s += v[k]; }
        s = warp_sum(s);
        float mu = s * (1.f / 256.f);
        float var = 0.f;
        #pragma unroll
        for (int k = 0; k < 8; k++) { float t = v[k] - mu; var = fmaf(t, t, var); }
        var = warp_sum(var);
        float rs = 1.0f / sqrtf(var * (1.f / 256.f) + 1e-5f);
        #pragma unroll
        for (int k = 0; k < 8; k++) {
            int d = lane + 32 * k;
            aP[d * 16 + rr] = (v[k] - mu) * rs * ln1_g[d] + ln1_b[d];
        }
    }
    __syncthreads();

    // qkv = h0 @ w_in^T + b_in  (row-major out for attention)
    for (int ch = 0; ch < 3; ++ch) {
        int col = ch * 256 + tid;
        ull res[8];
        dot16kp((const ulonglong2*)aP, g_wT_in, 768, col, res);
        float bi = b_in[col];
        #pragma unroll
        for (int p = 0; p < 8; p++) {
            float lo, hi; unpack2(lo, hi, res[p]);
            qkv[(2 * p) * 768 + col]     = __fadd_rn(lo, bi);
            qkv[(2 * p + 1) * 768 + col] = __fadd_rn(hi, bi);
        }
    }
    __syncthreads();

    // scores: 2 tokens x 2 heads x 64 (l,m) = 256 threads
    {
        int t = tid >> 7, h = (tid >> 6) & 1, rem = tid & 63, l = rem >> 3, m = rem & 7;
        const float* q  = &qkv[(t * 8 + l) * 768 + h * 128];
        const float* kk = &qkv[(t * 8 + m) * 768 + 256 + h * 128];
        float a0 = 0.f, a1 = 0.f, a2 = 0.f, a3 = 0.f;
        #pragma unroll 8
        for (int d = 0; d < 128; d += 4) {
            a0 = fmaf(q[d],     kk[d],     a0);
            a1 = fmaf(q[d + 1], kk[d + 1], a1);
            a2 = fmaf(q[d + 2], kk[d + 2], a2);
            a3 = fmaf(q[d + 3], kk[d + 3], a3);
        }
        float s = __fadd_rn(__fadd_rn(a0, a1), __fadd_rn(a2, a3));
        sc[((t * 2 + h) * 8 + l) * 8 + m] = s / 11.313708498984760f;
    }
    __syncthreads();

    // softmax over m: 32 rows (2 tokens x 2 heads x 8 l)
    if (tid < 32) {
        float* row = &sc[tid * 8];
        float mx = row[0];
        #pragma unroll
        for (int m = 1; m < 8; m++) mx = fmaxf(mx, row[m]);
        float e[8], sm = 0.f;
        #pragma unroll
        for (int m = 0; m < 8; m++) { e[m] = expf(row[m] - mx); sm += e[m]; }
        float inv = 1.f / sm;
        #pragma unroll
        for (int m = 0; m < 8; m++) row[m] = e[m] * inv;
    }
    __syncthreads();

    // o = a @ v -> aP (pair layout, 16 rows)
    {
        int e = tid, h = e >> 7;
        float sl[16];
        #pragma unroll
        for (int t = 0; t < 2; t++) {
            #pragma unroll
            for (int l = 0; l < 8; l++) {
                float s = 0.f;
                #pragma unroll
                for (int m = 0; m < 8; m++)
                    s = fmaf(sc[((t * 2 + h) * 8 + l) * 8 + m],
                             qkv[(t * 8 + m) * 768 + 512 + e], s);
                sl[t * 8 + l] = s;
            }
        }
        __syncthreads();   // aP reads (qkv GEMM) + qkv reads done
        #pragma unroll
        for (int p = 0; p < 8; p++)
            *(ull*)&aP[e * 16 + 2 * p] = pack2(sl[2 * p], sl[2 * p + 1]);
    }
    __syncthreads();

    // proj + residual (pair)
    {
        int col = tid;
        ull res[8];
        dot16kp((const ulonglong2*)aP, g_wT_out, 256, col, res);
        float bo = b_out[col];
        ull bop = pack2(bo, bo);
        #pragma unroll
        for (int p = 0; p < 8; p++) {
            ull old = *(ull*)&flatP[col * 16 + 2 * p];
            *(ull*)&flatP[col * 16 + 2 * p] = add2(add2(res[p], bop), old);
        }
    }
    __syncthreads();

    // LN2
    #pragma unroll
    for (int rr = w; rr < 16; rr += 8) {
        float v[8];
        float s = 0.f;
        #pragma unroll
        for (int k = 0; k < 8; k++) { v[k] = flatP[(lane + 32 * k) * 16 + rr]; s += v[k]; }
        s = warp_sum(s);
        float mu = s * (1.f / 256.f);
        float var = 0.f;
        #pragma unroll
        for (int k = 0; k < 8; k++) { float t = v[k] - mu; var = fmaf(t, t, var); }
        var = warp_sum(var);
        float rs = 1.0f / sqrtf(var * (1.f / 256.f) + 1e-5f);
        #pragma unroll
        for (int k = 0; k < 8; k++) {
            int d = lane + 32 * k;
            aP[d * 16 + rr] = (v[k] - mu) * rs * ln2_g[d] + ln2_b[d];
        }
    }
    __syncthreads();

    // ffn1 + gelu -> hP (pair; aliases qkv, which is dead now)
    {
        int col = tid;
        ull res[8];
        dot16kp((const ulonglong2*)aP, g_wT_f1, 256, col, res);
        float b1 = fb1[col];
        #pragma unroll
        for (int p = 0; p < 8; p++) {
            float lo, hi; unpack2(lo, hi, res[p]);
            float u0 = __fadd_rn(lo, b1), u1 = __fadd_rn(hi, b1);
            float g0 = 0.5f * u0 * (1.0f + erff(u0 * 0.70710678118654752f));
            float g1 = 0.5f * u1 * (1.0f + erff(u1 * 0.70710678118654752f));
            *(ull*)&hP[col * 16 + 2 * p] = pack2(g0, g1);
        }
    }
    __syncthreads();

    // ffn2 + residual (pair)
    {
        int col = tid;
        ull res[8];
        dot16kp((const ulonglong2*)hP, g_wT_f2, 256, col, res);
        float b2 = fb2[col];
        ull b2p = pack2(b2, b2);
        #pragma unroll
        for (int p = 0; p < 8; p++) {
            ull old = *(ull*)&flatP[col * 16 + 2 * p];
            *(ull*)&flatP[col * 16 + 2 * p] = add2(add2(res[p], b2p), old);
        }
    }
    __syncthreads();

    // dec -> flatten (global, row-major (c,i))
    {
        int col = tid;
        ull res[8];
        dot16kp((const ulonglong2*)flatP, g_wT_dec, 256, col, res);
        float bd = db[col];
        #pragma unroll
        for (int p = 0; p < 8; p++) {
            float lo, hi; unpack2(lo, hi, res[p]);
            int gi = i0 + (p >> 2);
            int c0 = (2 * p) & 7, c1 = (2 * p + 1) & 7;
            out_flat[((size_t)c0 * BB + gi) * 256 + col] = __fadd_rn(lo, bd);
            out_flat[((size_t)c1 * BB + gi) * 256 + col] = __fadd_rn(hi, bd);
        }
    }
}

// ---------------------------------------------------------------- knorm ------
// fp64-accumulated |k|^2, rounded once to fp32: exact C32 for refine, and the
// (slightly more exact) score offset for dist.
__global__ void __launch_bounds__(256) knorm_kernel(const float* __restrict__ keys) {
    int gw = (blockIdx.x * 256 + threadIdx.x) >> 5;
    int lane = threadIdx.x & 31;
    if (gw >= CB * PP) return;
    const float* row = keys + (size_t)gw * 256;
    double s = 0.0;
    #pragma unroll
    for (int k = 0; k < 8; k++) {
        double t = (double)row[lane + 32 * k];
        s = fma(t, t, s);
    }
    s = warp_sum_d(s);
    if (lane == 0) g_knorm[gw] = (float)s;
}

// ---------------------------------------------------------------- Kernel B ---
// Fused distance GEMM (packed f32x2, 8 row-pairs) + 2-way j blocking + top-8.
__global__ void __launch_bounds__(256) dist_kernel(const float* __restrict__ flat)
{
    __shared__ __align__(16) float Fp[256 * 16];   // pair layout [d][8 pairs]
    __shared__ float S[16][517];
    __shared__ float mv[16][128];
    __shared__ unsigned short mi[16][128];

    int c = blockIdx.y, ib = blockIdx.x, tid = threadIdx.x;
    int i0 = ib * 16;
    int r = tid & 15, sub = tid >> 4;

    for (int idx = tid; idx < 1024; idx += 256) {
        int rr = idx >> 6, d4 = idx & 63;
        float4 v = *(const float4*)(flat + ((size_t)c * BB + i0 + rr) * 256 + d4 * 4);
        int off = (rr >> 1) * 2 + (rr & 1);
        Fp[(4 * d4 + 0) * 16 + off] = v.x;
        Fp[(4 * d4 + 1) * 16 + off] = v.y;
        Fp[(4 * d4 + 2) * 16 + off] = v.z;
        Fp[(4 * d4 + 3) * 16 + off] = v.w;
    }
    __syncthreads();

    float tv[NSHORT];
    int   ti[NSHORT];
    #pragma unroll
    for (int t = 0; t < NSHORT; ++t) { tv[t] = -1e30f; ti[t] = 0; }

    const ulonglong2* Fp2 = (const ulonglong2*)Fp;   // 4 per d

    for (int tile = 0; tile < 4; ++tile) {
        int j = tile * 512 + tid;
        const float4* kp = g_kT + (size_t)c * 64 * PP + j;
        ull acc0[8], acc1[8];
        #pragma unroll
        for (int p = 0; p < 8; ++p) { acc0[p] = 0ULL; acc1[p] = 0ULL; }
        #pragma unroll 2
        for (int d4 = 0; d4 < 64; ++d4) {
            float4 ka = __ldg(kp + (size_t)d4 * PP);
            float4 kb = __ldg(kp + (size_t)d4 * PP + 256);
            #pragma unroll
            for (int e = 0; e < 4; ++e) {
                int d = 4 * d4 + e;
                float kae = (&ka.x)[e], kbe = (&kb.x)[e];
                ull ka2 = pack2(kae, kae);
                ull kb2 = pack2(kbe, kbe);
                ulonglong2 f01 = Fp2[d * 4 + 0];
                ulonglong2 f23 = Fp2[d * 4 + 1];
                ulonglong2 f45 = Fp2[d * 4 + 2];
                ulonglong2 f67 = Fp2[d * 4 + 3];
                acc0[0] = fma2(f01.x, ka2, acc0[0]); acc0[1] = fma2(f01.y, ka2, acc0[1]);
                acc0[2] = fma2(f23.x, ka2, acc0[2]); acc0[3] = fma2(f23.y, ka2, acc0[3]);
                acc0[4] = fma2(f45.x, ka2, acc0[4]); acc0[5] = fma2(f45.y, ka2, acc0[5]);
                acc0[6] = fma2(f67.x, ka2, acc0[6]); acc0[7] = fma2(f67.y, ka2, acc0[7]);
                acc1[0] = fma2(f01.x, kb2, acc1[0]); acc1[1] = fma2(f01.y, kb2, acc1[1]);
                acc1[2] = fma2(f23.x, kb2, acc1[2]); acc1[3] = fma2(f23.y, kb2, acc1[3]);
                acc1[4] = fma2(f45.x, kb2, acc1[4]); acc1[5] = fma2(f45.y, kb2, acc1[5]);
                acc1[6] = fma2(f67.x, kb2, acc1[6]); acc1[7] = fma2(f67.y, kb2, acc1[7]);
            }
        }
        float kn0 = g_knorm[c * PP + j];
        float kn1 = g_knorm[c * PP + j + 256];
        #pragma unroll
        for (int p = 0; p < 8; ++p) {
            float a, b2v;
            unpack2(a, b2v, acc0[p]);
            S[2 * p][tid]     = fmaf(2.f, a,   -kn0);
            S[2 * p + 1][tid] = fmaf(2.f, b2v, -kn0);
            unpack2(a, b2v, acc1[p]);
            S[2 * p][tid + 256]     = fmaf(2.f, a,   -kn1);
            S[2 * p + 1][tid + 256] = fmaf(2.f, b2v, -kn1);
        }
        __syncthreads();
        // per-row top-8 scan: thread (r,sub) scans 32 ascending columns
        #pragma unroll 4
        for (int q = 0; q < 32; ++q) {
            int col = sub * 32 + q;
            float v = S[r][col];
            int jj = tile * 512 + col;
            if (v > tv[NSHORT - 1]) {
                tv[NSHORT - 1] = v; ti[NSHORT - 1] = jj;
                #pragma unroll
                for (int p = NSHORT - 1; p > 0; --p) {
                    if (tv[p] > tv[p - 1] || (tv[p] == tv[p - 1] && ti[p] < ti[p - 1])) {
                        float a = tv[p]; tv[p] = tv[p - 1]; tv[p - 1] = a;
                        int   b = ti[p]; ti[p] = ti[p - 1]; ti[p - 1] = b;
                    }
                }
            }
        }
        __syncthreads();
    }

    // merge 16 per-thread lists per row
    #pragma unroll
    for (int t = 0; t < NSHORT; ++t) {
        mv[r][sub * 8 + t] = tv[t];
        mi[r][sub * 8 + t] = (unsigned short)ti[t];
    }
    __syncthreads();

    if (tid < 16) {
        int row = tid;
        float fv[NSHORT];
        int   fi[NSHORT];
        #pragma unroll
        for (int t = 0; t < NSHORT; ++t) { fv[t] = -1e30f; fi[t] = 0; }
        for (int e = 0; e < 128; ++e) {
            float v = mv[row][e];
            int jj = (int)mi[row][e];
            if (v > fv[NSHORT - 1] || (v == fv[NSHORT - 1] && jj < fi[NSHORT - 1])) {
                fv[NSHORT - 1] = v; fi[NSHORT - 1] = jj;
                #pragma unroll
                for (int p = NSHORT - 1; p > 0; --p) {
                    if (fv[p] > fv[p - 1] || (fv[p] == fv[p - 1] && fi[p] < fi[p - 1])) {
                        float a = fv[p]; fv[p] = fv[p - 1]; fv[p - 1] = a;
                        int   b = fi[p]; fi[p] = fi[p - 1]; fi[p - 1] = b;
                    }
                }
            }
        }
        int ig = i0 + row;
        #pragma unroll
        for (int t = 0; t < NSHORT; ++t)
            g_short[((size_t)ig * 8 + c) * NSHORT + t] = fi[t];
    }
}

// ---------------------------------------------------------------- refine -----
// fp64 exact dot + pre-rounded C32 from knorm; fp32 tensor-boundary emulation
// of the reference dist, tie-break by lower index (jax.lax.top_k).
__global__ void __launch_bounds__(256) refine_kernel(
    const float* __restrict__ flat, const float* __restrict__ keys,
    const float* __restrict__ counter, float* __restrict__ out)
{
    int gw = (blockIdx.x * 256 + threadIdx.x) >> 5;   // row = i*8 + c
    int lane = threadIdx.x & 31;
    if (gw >= BB * CB) return;
    int i = gw >> 3, c = gw & 7;

    const float* frow = flat + ((size_t)c * BB + i) * 256;
    double f[8];
    double fn = 0.0;
    #pragma unroll
    for (int k = 0; k < 8; k++) {
        f[k] = (double)frow[lane + 32 * k];
        fn += f[k] * f[k];
    }
    fn = warp_sum_d(fn);

    float sv[NSHORT];
    int   si[NSHORT];
    float A32 = (float)fn;
    #pragma unroll
    for (int t = 0; t < NSHORT; ++t) {
        int idx = g_short[(size_t)gw * NSHORT + t];
        si[t] = idx;
        const float* krow = keys + ((size_t)c * PP + idx) * 256;
        double dot = 0.0;
        #pragma unroll
        for (int k = 0; k < 8; k++)
            dot = fma(f[k], (double)krow[lane + 32 * k], dot);
        dot = warp_sum_d(dot);
        float B32 = 2.0f * (float)dot;
        float C32 = __ldg(g_knorm + c * PP + idx);
        float t1  = __fadd_rn(A32, -B32);
        float t2  = __fadd_rn(t1, C32);
        sv[t] = -t2;
    }

    if (lane == 0) {
        #pragma unroll
        for (int a = 0; a < TK; ++a) {
            int best = a;
            #pragma unroll
            for (int b2 = a + 1; b2 < NSHORT; ++b2) {
                if (sv[b2] > sv[best] || (sv[b2] == sv[best] && si[b2] < si[best]))
                    best = b2;
            }
            float vtmp = sv[a]; sv[a] = sv[best]; sv[best] = vtmp;
            int   itmp = si[a]; si[a] = si[best]; si[best] = itmp;
            size_t o = ((size_t)i * 8 + c) * 4 + a;
            out[OFF_IND + o]  = (float)si[a];
            out[OFF_DIST + o] = sv[a];
            out[OFF_CNT + o]  = counter[c * PP + si[a]];
            g_idx[o] = si[a];
        }
    }
}

// ---------------------------------------------------------------- Kernel C ---
__global__ void __launch_bounds__(256) gather_kernel(
    const float* __restrict__ keys, const float* __restrict__ values,
    float* __restrict__ out)
{
    int gw = (blockIdx.x * 256 + threadIdx.x) >> 5;
    int lane = threadIdx.x & 31;
    int c = (gw >> 2) & 7;
    int idx = g_idx[gw];
    const float4* ks = (const float4*)(keys   + ((size_t)c * PP + idx) * 256);
    const float4* vs = (const float4*)(values + ((size_t)c * PP + idx) * 256);
    float4* oqk = (float4*)(out + OFF_QK) + (size_t)gw * 64;
    float4* oqv = (float4*)(out + OFF_QV) + (size_t)gw * 64;
    oqv[lane]      = vs[lane];
    oqv[lane + 32] = vs[lane + 32];
    oqk[lane]      = ks[lane];
    oqk[lane + 32] = ks[lane + 32];
}

// -----------------------------------------------------------------------------
#define ENC_SMEM 82944

extern "C" void kernel_launch(void* const* d_in, const int* in_sizes, int n_in,
                              void* d_out, int out_size) {
    const float* x       = (const float*)d_in[0];
    const float* keys    = (const float*)d_in[1];
    const float* values  = (const float*)d_in[2];
    const float* counter = (const float*)d_in[3];
    const float* ln1_g   = (const float*)d_in[4];
    const float* ln1_b   = (const float*)d_in[5];
    const float* w_in    = (const float*)d_in[6];
    const float* b_in    = (const float*)d_in[7];
    const float* w_out   = (const float*)d_in[8];
    const float* b_out   = (const float*)d_in[9];
    const float* ln2_g   = (const float*)d_in[10];
    const float* ln2_b   = (const float*)d_in[11];
    const float* fw1     = (const float*)d_in[12];
    const float* fb1     = (const float*)d_in[13];
    const float* fw2     = (const float*)d_in[14];
    const float* fb2     = (const float*)d_in[15];
    const float* dw      = (const float*)d_in[16];
    const float* db      = (const float*)d_in[17];
    float* out = (float*)d_out;

    cudaFuncSetAttribute(enc_kernel,
                         cudaFuncAttributeMaxDynamicSharedMemorySize, ENC_SMEM);

    float4* wt_in;  cudaGetSymbolAddress((void**)&wt_in,  g_wT_in);
    float4* wt_out; cudaGetSymbolAddress((void**)&wt_out, g_wT_out);
    float4* wt_f1;  cudaGetSymbolAddress((void**)&wt_f1,  g_wT_f1);
    float4* wt_f2;  cudaGetSymbolAddress((void**)&wt_f2,  g_wT_f2);
    float4* wt_dec; cudaGetSymbolAddress((void**)&wt_dec, g_wT_dec);

    transW_kernel<<<(64 * 768 + 255) / 256, 256>>>(w_in,  wt_in,  768);
    transW_kernel<<<(64 * 256 + 255) / 256, 256>>>(w_out, wt_out, 256);
    transW_kernel<<<(64 * 256 + 255) / 256, 256>>>(fw1,   wt_f1,  256);
    transW_kernel<<<(64 * 256 + 255) / 256, 256>>>(fw2,   wt_f2,  256);
    transW_kernel<<<(64 * 256 + 255) / 256, 256>>>(dw,    wt_dec, 256);

    enc_kernel<<<BB / 2, 256, ENC_SMEM>>>(x, ln1_g, ln1_b, b_in, b_out,
                                          ln2_g, ln2_b, fb1, fb2, db,
                                          out + OFF_FLAT);

    transK_kernel<<<CB * 64 * PP / 256, 256>>>(keys);
    knorm_kernel<<<2048, 256>>>(keys);

    dist_kernel<<<dim3(BB / 16, CB), 256>>>(out + OFF_FLAT);
    refine_kernel<<<BB * CB / 8, 256>>>(out + OFF_FLAT, keys, counter, out);
    gather_kernel<<<32768, 256>>>(keys, values, out);
}

// round 15
// speedup vs baseline: 1.8222x; 1.0031x over previous
#include <cuda_runtime.h>
#include <math.h>
#include <stdint.h>

#define CB   8
#define PP   2048
#define DKx  256
#define BB   8192
#define TK   4

// output offsets (elements, fp32)
#define OFF_QV   0ULL
#define OFF_QK   67108864ULL
#define OFF_IND  134217728ULL
#define OFF_DIST 134479872ULL
#define OFF_CNT  134742016ULL
#define OFF_FLAT 135004160ULL

#define NSHORT 8

typedef unsigned long long ull;

__device__ int    g_idx[BB * CB * TK];
__device__ int    g_short[BB * CB * NSHORT];
__device__ float  g_knorm[CB * PP];     // fp64-accumulated, fp32-rounded |k|^2
// transposed keys: coalesced float4 over contraction dim [(c*64 + d4)*2048 + j]
__device__ float4 g_kT[CB * 64 * PP];
// transposed weights for enc (coalesced float4 over contraction dim)
__device__ float4 g_wT_in[64 * 768];       // [d4*768 + col]
__device__ float4 g_wT_out[64 * 256];
__device__ float4 g_wT_f1[64 * 256];
__device__ float4 g_wT_f2[64 * 256];
__device__ float4 g_wT_dec[64 * 256];

// --------------------------------------------------------- packed f32x2 ----
__device__ __forceinline__ ull pack2(float lo, float hi) {
    ull r; asm("mov.b64 %0,{%1,%2};" : "=l"(r) : "f"(lo), "f"(hi)); return r;
}
__device__ __forceinline__ void unpack2(float& lo, float& hi, ull v) {
    asm("mov.b64 {%0,%1},%2;" : "=f"(lo), "=f"(hi) : "l"(v));
}
__device__ __forceinline__ ull fma2(ull a, ull b, ull c) {
    ull d; asm("fma.rn.f32x2 %0,%1,%2,%3;" : "=l"(d) : "l"(a), "l"(b), "l"(c)); return d;
}
__device__ __forceinline__ ull add2(ull a, ull b) {
    ull d; asm("add.rn.f32x2 %0,%1,%2;" : "=l"(d) : "l"(a), "l"(b)); return d;
}
__device__ __forceinline__ ull mul2(ull a, ull b) {
    ull d; asm("mul.rn.f32x2 %0,%1,%2;" : "=l"(d) : "l"(a), "l"(b)); return d;
}
// Kahan on packed pairs; fma2(x,-1,y) rounds identically to sub(y,x).
__device__ __forceinline__ void kadd2(ull& s, ull& c, ull v) {
    const ull neg1 = 0xBF800000BF800000ULL;
    ull y = fma2(c, neg1, v);
    ull t = add2(s, y);
    c = fma2(y, neg1, fma2(s, neg1, t));
    s = t;
}

__device__ __forceinline__ float warp_sum(float v) {
    #pragma unroll
    for (int o = 16; o; o >>= 1) v += __shfl_xor_sync(0xffffffffu, v, o);
    return v;
}
__device__ __forceinline__ double warp_sum_d(double v) {
    #pragma unroll
    for (int o = 16; o; o >>= 1) v += __shfl_xor_sync(0xffffffffu, v, o);
    return v;
}

// ------------------------------------------------------------- transposes ---
// merged: blocks [0,192)=w_in, [192,256)=w_out, [256,320)=fw1,
// [320,384)=fw2, [384,448)=dw
__global__ void __launch_bounds__(256) transW_kernel(
    const float* __restrict__ w_in,  const float* __restrict__ w_out,
    const float* __restrict__ fw1,   const float* __restrict__ fw2,
    const float* __restrict__ dw) {
    int b = blockIdx.x;
    const float* src; float4* dst; int NC; int base;
    if (b < 192)      { src = w_in;  dst = g_wT_in;  NC = 768; base = b; }
    else if (b < 256) { src = w_out; dst = g_wT_out; NC = 256; base = b - 192; }
    else if (b < 320) { src = fw1;   dst = g_wT_f1;  NC = 256; base = b - 256; }
    else if (b < 384) { src = fw2;   dst = g_wT_f2;  NC = 256; base = b - 320; }
    else              { src = dw;    dst = g_wT_dec; NC = 256; base = b - 384; }
    int idx = base * 256 + threadIdx.x;
    if (idx >= 64 * NC) return;
    int d4 = idx / NC, col = idx % NC;
    const float* p = src + (size_t)col * 256 + 4 * d4;
    dst[idx] = make_float4(p[0], p[1], p[2], p[3]);
}

__global__ void __launch_bounds__(256) transK_kernel(const float* __restrict__ keys) {
    int idx = blockIdx.x * 256 + threadIdx.x;           // ((c*64+d4)*2048 + j)
    int j = idx & 2047, rest = idx >> 11;
    int d4 = rest & 63, c = rest >> 6;
    const float* p = keys + ((size_t)(c * PP + j)) * 256 + 4 * d4;
    g_kT[idx] = make_float4(p[0], p[1], p[2], p[3]);
}

// Packed compensated dot over 16 rows (8 pairs): 32-MAC serial chunks; two
// chunks joined with add2, kadd2 every second chunk (Kahan chain preserved).
__device__ __forceinline__ void dot16kp(const ulonglong2* __restrict__ Ap,
                                        const float4* __restrict__ wT4, int NC, int col,
                                        ull* out) {
    ull s[8], c[8], half[8];
    #pragma unroll
    for (int p = 0; p < 8; p++) { s[p] = 0ULL; c[p] = 0ULL; }
    #pragma unroll 2
    for (int g = 0; g < 8; ++g) {
        float4 w[8];
        #pragma unroll
        for (int q = 0; q < 8; ++q)
            w[q] = __ldg(wT4 + (size_t)(8 * g + q) * NC + col);
        ull ch[8];
        {
            ull wp = pack2(w[0].x, w[0].x);
            ulonglong2 a01 = Ap[(g * 32) * 4 + 0];
            ulonglong2 a23 = Ap[(g * 32) * 4 + 1];
            ulonglong2 a45 = Ap[(g * 32) * 4 + 2];
            ulonglong2 a67 = Ap[(g * 32) * 4 + 3];
            ch[0] = mul2(a01.x, wp); ch[1] = mul2(a01.y, wp);
            ch[2] = mul2(a23.x, wp); ch[3] = mul2(a23.y, wp);
            ch[4] = mul2(a45.x, wp); ch[5] = mul2(a45.y, wp);
            ch[6] = mul2(a67.x, wp); ch[7] = mul2(a67.y, wp);
        }
        #pragma unroll
        for (int dd = 1; dd < 32; ++dd) {
            float we = (&w[dd >> 2].x)[dd & 3];
            ull wp = pack2(we, we);
            int d = g * 32 + dd;
            ulonglong2 a01 = Ap[d * 4 + 0];
            ulonglong2 a23 = Ap[d * 4 + 1];
            ulonglong2 a45 = Ap[d * 4 + 2];
            ulonglong2 a67 = Ap[d * 4 + 3];
            ch[0] = fma2(a01.x, wp, ch[0]); ch[1] = fma2(a01.y, wp, ch[1]);
            ch[2] = fma2(a23.x, wp, ch[2]); ch[3] = fma2(a23.y, wp, ch[3]);
            ch[4] = fma2(a45.x, wp, ch[4]); ch[5] = fma2(a45.y, wp, ch[5]);
            ch[6] = fma2(a67.x, wp, ch[6]); ch[7] = fma2(a67.y, wp, ch[7]);
        }
        if ((g & 1) == 0) {
            #pragma unroll
            for (int p = 0; p < 8; p++) half[p] = ch[p];
        } else {
            #pragma unroll
            for (int p = 0; p < 8; p++) kadd2(s[p], c[p], add2(half[p], ch[p]));
        }
    }
    #pragma unroll
    for (int p = 0; p < 8; p++) out[p] = add2(s[p], c[p]);
}

// ---------------------------------------------------------------- Kernel A ---
// 2 tokens per CTA: 16 residual rows, pair layout buf[d*16 + row].
__global__ void __launch_bounds__(256, 2) enc_kernel(
    const float* __restrict__ x,
    const float* __restrict__ ln1_g, const float* __restrict__ ln1_b,
    const float* __restrict__ b_in,  const float* __restrict__ b_out,
    const float* __restrict__ ln2_g, const float* __restrict__ ln2_b,
    const float* __restrict__ fb1,   const float* __restrict__ fb2,
    const float* __restrict__ db,
    float* __restrict__ out_flat)
{
    extern __shared__ __align__(16) float smem_dyn[];
    float* flatP = smem_dyn;                 // 4096 floats
    float* aP    = smem_dyn + 4096;          // 4096 floats
    float* qkv   = smem_dyn + 8192;          // 12288 floats [16][768]
    float* sc    = smem_dyn + 20480;         // 256 floats [2][2][8][8]
    float* hP    = qkv;                      // ffn hidden (pair), aliases qkv

    int i0 = blockIdx.x * 2, tid = threadIdx.x;
    int w = tid >> 5, lane = tid & 31;

    // stage x (2 tokens) into pair layout: off == row
    for (int idx = tid; idx < 1024; idx += 256) {
        int l = idx >> 6, d4 = idx & 63;          // l = row 0..15
        int gi = i0 + (l >> 3);
        float4 v = *(const float4*)(x + ((size_t)gi * 8 + (l & 7)) * 256 + 4 * d4);
        flatP[(4 * d4 + 0) * 16 + l] = v.x;
        flatP[(4 * d4 + 1) * 16 + l] = v.y;
        flatP[(4 * d4 + 2) * 16 + l] = v.z;
        flatP[(4 * d4 + 3) * 16 + l] = v.w;
    }
    __syncthreads();

    // LN1: each warp handles rows w and w+8
    #pragma unroll
    for (int rr = w; rr < 16; rr += 8) {
        float v[8];
        float s = 0.f;
        #pragma unroll
        for (int k = 0; k < 8; k++) { v[k] = flatP[(lane + 32 * k) * 16 + rr]; s += v[k]; }
        s = warp_sum(s);
        float mu = s * (1.f / 256.f);
        float var = 0.f;
        #pragma unroll
        for (int k = 0; k < 8; k++) { float t = v[k] - mu; var = fmaf(t, t, var); }
        var = warp_sum(var);
        float rs = 1.0f / sqrtf(var * (1.f / 256.f) + 1e-5f);
        #pragma unroll
        for (int k = 0; k < 8; k++) {
            int d = lane + 32 * k;
            aP[d * 16 + rr] = (v[k] - mu) * rs * ln1_g[d] + ln1_b[d];
        }
    }
    __syncthreads();

    // qkv = h0 @ w_in^T + b_in  (row-major out for attention)
    for (int ch = 0; ch < 3; ++ch) {
        int col = ch * 256 + tid;
        ull res[8];
        dot16kp((const ulonglong2*)aP, g_wT_in, 768, col, res);
        float bi = b_in[col];
        #pragma unroll
        for (int p = 0; p < 8; p++) {
            float lo, hi; unpack2(lo, hi, res[p]);
            qkv[(2 * p) * 768 + col]     = __fadd_rn(lo, bi);
            qkv[(2 * p + 1) * 768 + col] = __fadd_rn(hi, bi);
        }
    }
    __syncthreads();

    // scores: 2 tokens x 2 heads x 64 (l,m) = 256 threads
    {
        int t = tid >> 7, h = (tid >> 6) & 1, rem = tid & 63, l = rem >> 3, m = rem & 7;
        const float* q  = &qkv[(t * 8 + l) * 768 + h * 128];
        const float* kk = &qkv[(t * 8 + m) * 768 + 256 + h * 128];
        float a0 = 0.f, a1 = 0.f, a2 = 0.f, a3 = 0.f;
        #pragma unroll 8
        for (int d = 0; d < 128; d += 4) {
            a0 = fmaf(q[d],     kk[d],     a0);
            a1 = fmaf(q[d + 1], kk[d + 1], a1);
            a2 = fmaf(q[d + 2], kk[d + 2], a2);
            a3 = fmaf(q[d + 3], kk[d + 3], a3);
        }
        float s = __fadd_rn(__fadd_rn(a0, a1), __fadd_rn(a2, a3));
        sc[((t * 2 + h) * 8 + l) * 8 + m] = s / 11.313708498984760f;
    }
    __syncthreads();

    // softmax over m: 32 rows (2 tokens x 2 heads x 8 l)
    if (tid < 32) {
        float* row = &sc[tid * 8];
        float mx = row[0];
        #pragma unroll
        for (int m = 1; m < 8; m++) mx = fmaxf(mx, row[m]);
        float e[8], sm = 0.f;
        #pragma unroll
        for (int m = 0; m < 8; m++) { e[m] = expf(row[m] - mx); sm += e[m]; }
        float inv = 1.f / sm;
        #pragma unroll
        for (int m = 0; m < 8; m++) row[m] = e[m] * inv;
    }
    __syncthreads();

    // o = a @ v -> aP (pair layout, 16 rows)
    {
        int e = tid, h = e >> 7;
        float sl[16];
        #pragma unroll
        for (int t = 0; t < 2; t++) {
            #pragma unroll
            for (int l = 0; l < 8; l++) {
                float s = 0.f;
                #pragma unroll
                for (int m = 0; m < 8; m++)
                    s = fmaf(sc[((t * 2 + h) * 8 + l) * 8 + m],
                             qkv[(t * 8 + m) * 768 + 512 + e], s);
                sl[t * 8 + l] = s;
            }
        }
        __syncthreads();   // aP reads (qkv GEMM) + qkv reads done
        #pragma unroll
        for (int p = 0; p < 8; p++)
            *(ull*)&aP[e * 16 + 2 * p] = pack2(sl[2 * p], sl[2 * p + 1]);
    }
    __syncthreads();

    // proj + residual (pair)
    {
        int col = tid;
        ull res[8];
        dot16kp((const ulonglong2*)aP, g_wT_out, 256, col, res);
        float bo = b_out[col];
        ull bop = pack2(bo, bo);
        #pragma unroll
        for (int p = 0; p < 8; p++) {
            ull old = *(ull*)&flatP[col * 16 + 2 * p];
            *(ull*)&flatP[col * 16 + 2 * p] = add2(add2(res[p], bop), old);
        }
    }
    __syncthreads();

    // LN2
    #pragma unroll
    for (int rr = w; rr < 16; rr += 8) {
        float v[8];
        float s = 0.f;
        #pragma unroll
        for (int k = 0; k < 8; k++) { v[k] = flatP[(lane + 32 * k) * 16 + rr]; s += v[k]; }
        s = warp_sum(s);
        float mu = s * (1.f / 256.f);
        float var = 0.f;
        #pragma unroll
        for (int k = 0; k < 8; k++) { float t = v[k] - mu; var = fmaf(t, t, var); }
        var = warp_sum(var);
        float rs = 1.0f / sqrtf(var * (1.f / 256.f) + 1e-5f);
        #pragma unroll
        for (int k = 0; k < 8; k++) {
            int d = lane + 32 * k;
            aP[d * 16 + rr] = (v[k] - mu) * rs * ln2_g[d] + ln2_b[d];
        }
    }
    __syncthreads();

    // ffn1 + gelu -> hP (pair; aliases qkv, which is dead now)
    {
        int col = tid;
        ull res[8];
        dot16kp((const ulonglong2*)aP, g_wT_f1, 256, col, res);
        float b1 = fb1[col];
        #pragma unroll
        for (int p = 0; p < 8; p++) {
            float lo, hi; unpack2(lo, hi, res[p]);
            float u0 = __fadd_rn(lo, b1), u1 = __fadd_rn(hi, b1);
            float g0 = 0.5f * u0 * (1.0f + erff(u0 * 0.70710678118654752f));
            float g1 = 0.5f * u1 * (1.0f + erff(u1 * 0.70710678118654752f));
            *(ull*)&hP[col * 16 + 2 * p] = pack2(g0, g1);
        }
    }
    __syncthreads();

    // ffn2 + residual (pair)
    {
        int col = tid;
        ull res[8];
        dot16kp((const ulonglong2*)hP, g_wT_f2, 256, col, res);
        float b2 = fb2[col];
        ull b2p = pack2(b2, b2);
        #pragma unroll
        for (int p = 0; p < 8; p++) {
            ull old = *(ull*)&flatP[col * 16 + 2 * p];
            *(ull*)&flatP[col * 16 + 2 * p] = add2(add2(res[p], b2p), old);
        }
    }
    __syncthreads();

    // dec -> flatten (global, row-major (c,i))
    {
        int col = tid;
        ull res[8];
        dot16kp((const ulonglong2*)flatP, g_wT_dec, 256, col, res);
        float bd = db[col];
        #pragma unroll
        for (int p = 0; p < 8; p++) {
            float lo, hi; unpack2(lo, hi, res[p]);
            int gi = i0 + (p >> 2);
            int c0 = (2 * p) & 7, c1 = (2 * p + 1) & 7;
            out_flat[((size_t)c0 * BB + gi) * 256 + col] = __fadd_rn(lo, bd);
            out_flat[((size_t)c1 * BB + gi) * 256 + col] = __fadd_rn(hi, bd);
        }
    }
}

// ---------------------------------------------------------------- knorm ------
__global__ void __launch_bounds__(256) knorm_kernel(const float* __restrict__ keys) {
    int gw = (blockIdx.x * 256 + threadIdx.x) >> 5;
    int lane = threadIdx.x & 31;
    if (gw >= CB * PP) return;
    const float* row = keys + (size_t)gw * 256;
    double s = 0.0;
    #pragma unroll
    for (int k = 0; k < 8; k++) {
        double t = (double)row[lane + 32 * k];
        s = fma(t, t, s);
    }
    s = warp_sum_d(s);
    if (lane == 0) g_knorm[gw] = (float)s;
}

// ---------------------------------------------------------------- Kernel B ---
// Fused distance GEMM (packed f32x2, 8 row-pairs) + 2-way j blocking + top-8.
__global__ void __launch_bounds__(256) dist_kernel(const float* __restrict__ flat)
{
    __shared__ __align__(16) float Fp[256 * 16];   // pair layout [d][8 pairs]
    __shared__ float S[16][517];
    __shared__ float mv[16][128];
    __shared__ unsigned short mi[16][128];

    int c = blockIdx.y, ib = blockIdx.x, tid = threadIdx.x;
    int i0 = ib * 16;
    int r = tid & 15, sub = tid >> 4;

    for (int idx = tid; idx < 1024; idx += 256) {
        int rr = idx >> 6, d4 = idx & 63;
        float4 v = *(const float4*)(flat + ((size_t)c * BB + i0 + rr) * 256 + d4 * 4);
        int off = (rr >> 1) * 2 + (rr & 1);
        Fp[(4 * d4 + 0) * 16 + off] = v.x;
        Fp[(4 * d4 + 1) * 16 + off] = v.y;
        Fp[(4 * d4 + 2) * 16 + off] = v.z;
        Fp[(4 * d4 + 3) * 16 + off] = v.w;
    }
    __syncthreads();

    float tv[NSHORT];
    int   ti[NSHORT];
    #pragma unroll
    for (int t = 0; t < NSHORT; ++t) { tv[t] = -1e30f; ti[t] = 0; }

    const ulonglong2* Fp2 = (const ulonglong2*)Fp;   // 4 per d

    for (int tile = 0; tile < 4; ++tile) {
        int j = tile * 512 + tid;
        const float4* kp = g_kT + (size_t)c * 64 * PP + j;
        ull acc0[8], acc1[8];
        #pragma unroll
        for (int p = 0; p < 8; ++p) { acc0[p] = 0ULL; acc1[p] = 0ULL; }
        #pragma unroll 2
        for (int d4 = 0; d4 < 64; ++d4) {
            float4 ka = __ldg(kp + (size_t)d4 * PP);
            float4 kb = __ldg(kp + (size_t)d4 * PP + 256);
            #pragma unroll
            for (int e = 0; e < 4; ++e) {
                int d = 4 * d4 + e;
                float kae = (&ka.x)[e], kbe = (&kb.x)[e];
                ull ka2 = pack2(kae, kae);
                ull kb2 = pack2(kbe, kbe);
                ulonglong2 f01 = Fp2[d * 4 + 0];
                ulonglong2 f23 = Fp2[d * 4 + 1];
                ulonglong2 f45 = Fp2[d * 4 + 2];
                ulonglong2 f67 = Fp2[d * 4 + 3];
                acc0[0] = fma2(f01.x, ka2, acc0[0]); acc0[1] = fma2(f01.y, ka2, acc0[1]);
                acc0[2] = fma2(f23.x, ka2, acc0[2]); acc0[3] = fma2(f23.y, ka2, acc0[3]);
                acc0[4] = fma2(f45.x, ka2, acc0[4]); acc0[5] = fma2(f45.y, ka2, acc0[5]);
                acc0[6] = fma2(f67.x, ka2, acc0[6]); acc0[7] = fma2(f67.y, ka2, acc0[7]);
                acc1[0] = fma2(f01.x, kb2, acc1[0]); acc1[1] = fma2(f01.y, kb2, acc1[1]);
                acc1[2] = fma2(f23.x, kb2, acc1[2]); acc1[3] = fma2(f23.y, kb2, acc1[3]);
                acc1[4] = fma2(f45.x, kb2, acc1[4]); acc1[5] = fma2(f45.y, kb2, acc1[5]);
                acc1[6] = fma2(f67.x, kb2, acc1[6]); acc1[7] = fma2(f67.y, kb2, acc1[7]);
            }
        }
        float kn0 = g_knorm[c * PP + j];
        float kn1 = g_knorm[c * PP + j + 256];
        #pragma unroll
        for (int p = 0; p < 8; ++p) {
            float a, b2v;
            unpack2(a, b2v, acc0[p]);
            S[2 * p][tid]     = fmaf(2.f, a,   -kn0);
            S[2 * p + 1][tid] = fmaf(2.f, b2v, -kn0);
            unpack2(a, b2v, acc1[p]);
            S[2 * p][tid + 256]     = fmaf(2.f, a,   -kn1);
            S[2 * p + 1][tid + 256] = fmaf(2.f, b2v, -kn1);
        }
        __syncthreads();
        // per-row top-8 scan: thread (r,sub) scans 32 ascending columns
        #pragma unroll 4
        for (int q = 0; q < 32; ++q) {
            int col = sub * 32 + q;
            float v = S[r][col];
            int jj = tile * 512 + col;
            if (v > tv[NSHORT - 1]) {
                tv[NSHORT - 1] = v; ti[NSHORT - 1] = jj;
                #pragma unroll
                for (int p = NSHORT - 1; p > 0; --p) {
                    if (tv[p] > tv[p - 1] || (tv[p] == tv[p - 1] && ti[p] < ti[p - 1])) {
                        float a = tv[p]; tv[p] = tv[p - 1]; tv[p - 1] = a;
                        int   b = ti[p]; ti[p] = ti[p - 1]; ti[p - 1] = b;
                    }
                }
            }
        }
        __syncthreads();
    }

    // merge 16 per-thread lists per row
    #pragma unroll
    for (int t = 0; t < NSHORT; ++t) {
        mv[r][sub * 8 + t] = tv[t];
        mi[r][sub * 8 + t] = (unsigned short)ti[t];
    }
    __syncthreads();

    if (tid < 16) {
        int row = tid;
        float fv[NSHORT];
        int   fi[NSHORT];
        #pragma unroll
        for (int t = 0; t < NSHORT; ++t) { fv[t] = -1e30f; fi[t] = 0; }
        for (int e = 0; e < 128; ++e) {
            float v = mv[row][e];
            int jj = (int)mi[row][e];
            if (v > fv[NSHORT - 1] || (v == fv[NSHORT - 1] && jj < fi[NSHORT - 1])) {
                fv[NSHORT - 1] = v; fi[NSHORT - 1] = jj;
                #pragma unroll
                for (int p = NSHORT - 1; p > 0; --p) {
                    if (fv[p] > fv[p - 1] || (fv[p] == fv[p - 1] && fi[p] < fi[p - 1])) {
                        float a = fv[p]; fv[p] = fv[p - 1]; fv[p - 1] = a;
                        int   b = fi[p]; fi[p] = fi[p - 1]; fi[p - 1] = b;
                    }
                }
            }
        }
        int ig = i0 + row;
        #pragma unroll
        for (int t = 0; t < NSHORT; ++t)
            g_short[((size_t)ig * 8 + c) * NSHORT + t] = fi[t];
    }
}

// ---------------------------------------------------------------- refine -----
// fp64 exact dot + pre-rounded C32 from knorm; fp32 tensor-boundary emulation
// of the reference dist, tie-break by lower index (jax.lax.top_k).
__global__ void __launch_bounds__(256) refine_kernel(
    const float* __restrict__ flat, const float* __restrict__ keys,
    const float* __restrict__ counter, float* __restrict__ out)
{
    int gw = (blockIdx.x * 256 + threadIdx.x) >> 5;   // row = i*8 + c
    int lane = threadIdx.x & 31;
    if (gw >= BB * CB) return;
    int i = gw >> 3, c = gw & 7;

    const float* frow = flat + ((size_t)c * BB + i) * 256;
    double f[8];
    double fn = 0.0;
    #pragma unroll
    for (int k = 0; k < 8; k++) {
        f[k] = (double)frow[lane + 32 * k];
        fn += f[k] * f[k];
    }
    fn = warp_sum_d(fn);

    float sv[NSHORT];
    int   si[NSHORT];
    float A32 = (float)fn;
    #pragma unroll
    for (int t = 0; t < NSHORT; ++t) {
        int idx = g_short[(size_t)gw * NSHORT + t];
        si[t] = idx;
        const float* krow = keys + ((size_t)c * PP + idx) * 256;
        double dot = 0.0;
        #pragma unroll
        for (int k = 0; k < 8; k++)
            dot = fma(f[k], (double)krow[lane + 32 * k], dot);
        dot = warp_sum_d(dot);
        float B32 = 2.0f * (float)dot;
        float C32 = __ldg(g_knorm + c * PP + idx);
        float t1  = __fadd_rn(A32, -B32);
        float t2  = __fadd_rn(t1, C32);
        sv[t] = -t2;
    }

    if (lane == 0) {
        #pragma unroll
        for (int a = 0; a < TK; ++a) {
            int best = a;
            #pragma unroll
            for (int b2 = a + 1; b2 < NSHORT; ++b2) {
                if (sv[b2] > sv[best] || (sv[b2] == sv[best] && si[b2] < si[best]))
                    best = b2;
            }
            float vtmp = sv[a]; sv[a] = sv[best]; sv[best] = vtmp;
            int   itmp = si[a]; si[a] = si[best]; si[best] = itmp;
            size_t o = ((size_t)i * 8 + c) * 4 + a;
            out[OFF_IND + o]  = (float)si[a];
            out[OFF_DIST + o] = sv[a];
            out[OFF_CNT + o]  = counter[c * PP + si[a]];
            g_idx[o] = si[a];
        }
    }
}

// ---------------------------------------------------------------- Kernel C ---
__global__ void __launch_bounds__(256) gather_kernel(
    const float* __restrict__ keys, const float* __restrict__ values,
    float* __restrict__ out)
{
    int gw = (blockIdx.x * 256 + threadIdx.x) >> 5;
    int lane = threadIdx.x & 31;
    int c = (gw >> 2) & 7;
    int idx = g_idx[gw];
    const float4* ks = (const float4*)(keys   + ((size_t)c * PP + idx) * 256);
    const float4* vs = (const float4*)(values + ((size_t)c * PP + idx) * 256);
    float4* oqk = (float4*)(out + OFF_QK) + (size_t)gw * 64;
    float4* oqv = (float4*)(out + OFF_QV) + (size_t)gw * 64;
    oqv[lane]      = vs[lane];
    oqv[lane + 32] = vs[lane + 32];
    oqk[lane]      = ks[lane];
    oqk[lane + 32] = ks[lane + 32];
}

// -----------------------------------------------------------------------------
#define ENC_SMEM 82944

extern "C" void kernel_launch(void* const* d_in, const int* in_sizes, int n_in,
                              void* d_out, int out_size) {
    const float* x       = (const float*)d_in[0];
    const float* keys    = (const float*)d_in[1];
    const float* values  = (const float*)d_in[2];
    const float* counter = (const float*)d_in[3];
    const float* ln1_g   = (const float*)d_in[4];
    const float* ln1_b   = (const float*)d_in[5];
    const float* w_in    = (const float*)d_in[6];
    const float* b_in    = (const float*)d_in[7];
    const float* w_out   = (const float*)d_in[8];
    const float* b_out   = (const float*)d_in[9];
    const float* ln2_g   = (const float*)d_in[10];
    const float* ln2_b   = (const float*)d_in[11];
    const float* fw1     = (const float*)d_in[12];
    const float* fb1     = (const float*)d_in[13];
    const float* fw2     = (const float*)d_in[14];
    const float* fb2     = (const float*)d_in[15];
    const float* dw      = (const float*)d_in[16];
    const float* db      = (const float*)d_in[17];
    float* out = (float*)d_out;

    cudaFuncSetAttribute(enc_kernel,
                         cudaFuncAttributeMaxDynamicSharedMemorySize, ENC_SMEM);

    transW_kernel<<<448, 256>>>(w_in, w_out, fw1, fw2, dw);

    enc_kernel<<<BB / 2, 256, ENC_SMEM>>>(x, ln1_g, ln1_b, b_in, b_out,
                                          ln2_g, ln2_b, fb1, fb2, db,
                                          out + OFF_FLAT);

    transK_kernel<<<CB * 64 * PP / 256, 256>>>(keys);
    knorm_kernel<<<2048, 256>>>(keys);

    dist_kernel<<<dim3(BB / 16, CB), 256>>>(out + OFF_FLAT);
    refine_kernel<<<BB * CB / 8, 256>>>(out + OFF_FLAT, keys, counter, out);
    gather_kernel<<<32768, 256>>>(keys, values, out);
}

// round 16
// speedup vs baseline: 1.8566x; 1.0189x over previous
#include <cuda_runtime.h>
#include <math.h>
#include <stdint.h>

#define CB   8
#define PP   2048
#define DKx  256
#define BB   8192
#define TK   4

// output offsets (elements, fp32)
#define OFF_QV   0ULL
#define OFF_QK   67108864ULL
#define OFF_IND  134217728ULL
#define OFF_DIST 134479872ULL
#define OFF_CNT  134742016ULL
#define OFF_FLAT 135004160ULL

#define NSHORT 8

typedef unsigned long long ull;

__device__ int    g_short[BB * CB * NSHORT];
__device__ float  g_knorm[CB * PP];     // fp64-accumulated, fp32-rounded |k|^2
// transposed keys: coalesced float4 over contraction dim [(c*64 + d4)*2048 + j]
__device__ float4 g_kT[CB * 64 * PP];
// transposed weights for enc (coalesced float4 over contraction dim)
__device__ float4 g_wT_in[64 * 768];       // [d4*768 + col]
__device__ float4 g_wT_out[64 * 256];
__device__ float4 g_wT_f1[64 * 256];
__device__ float4 g_wT_f2[64 * 256];
__device__ float4 g_wT_dec[64 * 256];

// --------------------------------------------------------- packed f32x2 ----
__device__ __forceinline__ ull pack2(float lo, float hi) {
    ull r; asm("mov.b64 %0,{%1,%2};" : "=l"(r) : "f"(lo), "f"(hi)); return r;
}
__device__ __forceinline__ void unpack2(float& lo, float& hi, ull v) {
    asm("mov.b64 {%0,%1},%2;" : "=f"(lo), "=f"(hi) : "l"(v));
}
__device__ __forceinline__ ull fma2(ull a, ull b, ull c) {
    ull d; asm("fma.rn.f32x2 %0,%1,%2,%3;" : "=l"(d) : "l"(a), "l"(b), "l"(c)); return d;
}
__device__ __forceinline__ ull add2(ull a, ull b) {
    ull d; asm("add.rn.f32x2 %0,%1,%2;" : "=l"(d) : "l"(a), "l"(b)); return d;
}
__device__ __forceinline__ ull mul2(ull a, ull b) {
    ull d; asm("mul.rn.f32x2 %0,%1,%2;" : "=l"(d) : "l"(a), "l"(b)); return d;
}
// Kahan on packed pairs; fma2(x,-1,y) rounds identically to sub(y,x).
__device__ __forceinline__ void kadd2(ull& s, ull& c, ull v) {
    const ull neg1 = 0xBF800000BF800000ULL;
    ull y = fma2(c, neg1, v);
    ull t = add2(s, y);
    c = fma2(y, neg1, fma2(s, neg1, t));
    s = t;
}

__device__ __forceinline__ float warp_sum(float v) {
    #pragma unroll
    for (int o = 16; o; o >>= 1) v += __shfl_xor_sync(0xffffffffu, v, o);
    return v;
}
__device__ __forceinline__ double warp_sum_d(double v) {
    #pragma unroll
    for (int o = 16; o; o >>= 1) v += __shfl_xor_sync(0xffffffffu, v, o);
    return v;
}

// ------------------------------------------------------------- transposes ---
// merged: blocks [0,192)=w_in, [192,256)=w_out, [256,320)=fw1,
// [320,384)=fw2, [384,448)=dw
__global__ void __launch_bounds__(256) transW_kernel(
    const float* __restrict__ w_in,  const float* __restrict__ w_out,
    const float* __restrict__ fw1,   const float* __restrict__ fw2,
    const float* __restrict__ dw) {
    int b = blockIdx.x;
    const float* src; float4* dst; int NC; int base;
    if (b < 192)      { src = w_in;  dst = g_wT_in;  NC = 768; base = b; }
    else if (b < 256) { src = w_out; dst = g_wT_out; NC = 256; base = b - 192; }
    else if (b < 320) { src = fw1;   dst = g_wT_f1;  NC = 256; base = b - 256; }
    else if (b < 384) { src = fw2;   dst = g_wT_f2;  NC = 256; base = b - 320; }
    else              { src = dw;    dst = g_wT_dec; NC = 256; base = b - 384; }
    int idx = base * 256 + threadIdx.x;
    if (idx >= 64 * NC) return;
    int d4 = idx / NC, col = idx % NC;
    const float* p = src + (size_t)col * 256 + 4 * d4;
    dst[idx] = make_float4(p[0], p[1], p[2], p[3]);
}

__global__ void __launch_bounds__(256) transK_kernel(const float* __restrict__ keys) {
    int idx = blockIdx.x * 256 + threadIdx.x;           // ((c*64+d4)*2048 + j)
    int j = idx & 2047, rest = idx >> 11;
    int d4 = rest & 63, c = rest >> 6;
    const float* p = keys + ((size_t)(c * PP + j)) * 256 + 4 * d4;
    g_kT[idx] = make_float4(p[0], p[1], p[2], p[3]);
}

// Packed compensated dot over 16 rows (8 pairs): 32-MAC serial chunks; two
// chunks joined with add2, kadd2 every second chunk (Kahan chain preserved).
__device__ __forceinline__ void dot16kp(const ulonglong2* __restrict__ Ap,
                                        const float4* __restrict__ wT4, int NC, int col,
                                        ull* out) {
    ull s[8], c[8], half[8];
    #pragma unroll
    for (int p = 0; p < 8; p++) { s[p] = 0ULL; c[p] = 0ULL; }
    #pragma unroll 2
    for (int g = 0; g < 8; ++g) {
        float4 w[8];
        #pragma unroll
        for (int q = 0; q < 8; ++q)
            w[q] = __ldg(wT4 + (size_t)(8 * g + q) * NC + col);
        ull ch[8];
        {
            ull wp = pack2(w[0].x, w[0].x);
            ulonglong2 a01 = Ap[(g * 32) * 4 + 0];
            ulonglong2 a23 = Ap[(g * 32) * 4 + 1];
            ulonglong2 a45 = Ap[(g * 32) * 4 + 2];
            ulonglong2 a67 = Ap[(g * 32) * 4 + 3];
            ch[0] = mul2(a01.x, wp); ch[1] = mul2(a01.y, wp);
            ch[2] = mul2(a23.x, wp); ch[3] = mul2(a23.y, wp);
            ch[4] = mul2(a45.x, wp); ch[5] = mul2(a45.y, wp);
            ch[6] = mul2(a67.x, wp); ch[7] = mul2(a67.y, wp);
        }
        #pragma unroll
        for (int dd = 1; dd < 32; ++dd) {
            float we = (&w[dd >> 2].x)[dd & 3];
            ull wp = pack2(we, we);
            int d = g * 32 + dd;
            ulonglong2 a01 = Ap[d * 4 + 0];
            ulonglong2 a23 = Ap[d * 4 + 1];
            ulonglong2 a45 = Ap[d * 4 + 2];
            ulonglong2 a67 = Ap[d * 4 + 3];
            ch[0] = fma2(a01.x, wp, ch[0]); ch[1] = fma2(a01.y, wp, ch[1]);
            ch[2] = fma2(a23.x, wp, ch[2]); ch[3] = fma2(a23.y, wp, ch[3]);
            ch[4] = fma2(a45.x, wp, ch[4]); ch[5] = fma2(a45.y, wp, ch[5]);
            ch[6] = fma2(a67.x, wp, ch[6]); ch[7] = fma2(a67.y, wp, ch[7]);
        }
        if ((g & 1) == 0) {
            #pragma unroll
            for (int p = 0; p < 8; p++) half[p] = ch[p];
        } else {
            #pragma unroll
            for (int p = 0; p < 8; p++) kadd2(s[p], c[p], add2(half[p], ch[p]));
        }
    }
    #pragma unroll
    for (int p = 0; p < 8; p++) out[p] = add2(s[p], c[p]);
}

// ---------------------------------------------------------------- Kernel A ---
// 2 tokens per CTA: 16 residual rows, pair layout buf[d*16 + row].
__global__ void __launch_bounds__(256, 2) enc_kernel(
    const float* __restrict__ x,
    const float* __restrict__ ln1_g, const float* __restrict__ ln1_b,
    const float* __restrict__ b_in,  const float* __restrict__ b_out,
    const float* __restrict__ ln2_g, const float* __restrict__ ln2_b,
    const float* __restrict__ fb1,   const float* __restrict__ fb2,
    const float* __restrict__ db,
    float* __restrict__ out_flat)
{
    extern __shared__ __align__(16) float smem_dyn[];
    float* flatP = smem_dyn;                 // 4096 floats
    float* aP    = smem_dyn + 4096;          // 4096 floats
    float* qkv   = smem_dyn + 8192;          // 12288 floats [16][768]
    float* sc    = smem_dyn + 20480;         // 256 floats [2][2][8][8]
    float* hP    = qkv;                      // ffn hidden (pair), aliases qkv

    int i0 = blockIdx.x * 2, tid = threadIdx.x;
    int w = tid >> 5, lane = tid & 31;

    // stage x (2 tokens) into pair layout: off == row
    for (int idx = tid; idx < 1024; idx += 256) {
        int l = idx >> 6, d4 = idx & 63;          // l = row 0..15
        int gi = i0 + (l >> 3);
        float4 v = *(const float4*)(x + ((size_t)gi * 8 + (l & 7)) * 256 + 4 * d4);
        flatP[(4 * d4 + 0) * 16 + l] = v.x;
        flatP[(4 * d4 + 1) * 16 + l] = v.y;
        flatP[(4 * d4 + 2) * 16 + l] = v.z;
        flatP[(4 * d4 + 3) * 16 + l] = v.w;
    }
    __syncthreads();

    // LN1: each warp handles rows w and w+8
    #pragma unroll
    for (int rr = w; rr < 16; rr += 8) {
        float v[8];
        float s = 0.f;
        #pragma unroll
        for (int k = 0; k < 8; k++) { v[k] = flatP[(lane + 32 * k) * 16 + rr]; s += v[k]; }
        s = warp_sum(s);
        float mu = s * (1.f / 256.f);
        float var = 0.f;
        #pragma unroll
        for (int k = 0; k < 8; k++) { float t = v[k] - mu; var = fmaf(t, t, var); }
        var = warp_sum(var);
        float rs = 1.0f / sqrtf(var * (1.f / 256.f) + 1e-5f);
        #pragma unroll
        for (int k = 0; k < 8; k++) {
            int d = lane + 32 * k;
            aP[d * 16 + rr] = (v[k] - mu) * rs * ln1_g[d] + ln1_b[d];
        }
    }
    __syncthreads();

    // qkv = h0 @ w_in^T + b_in  (row-major out for attention)
    for (int ch = 0; ch < 3; ++ch) {
        int col = ch * 256 + tid;
        ull res[8];
        dot16kp((const ulonglong2*)aP, g_wT_in, 768, col, res);
        float bi = b_in[col];
        #pragma unroll
        for (int p = 0; p < 8; p++) {
            float lo, hi; unpack2(lo, hi, res[p]);
            qkv[(2 * p) * 768 + col]     = __fadd_rn(lo, bi);
            qkv[(2 * p + 1) * 768 + col] = __fadd_rn(hi, bi);
        }
    }
    __syncthreads();

    // scores: 2 tokens x 2 heads x 64 (l,m) = 256 threads
    {
        int t = tid >> 7, h = (tid >> 6) & 1, rem = tid & 63, l = rem >> 3, m = rem & 7;
        const float* q  = &qkv[(t * 8 + l) * 768 + h * 128];
        const float* kk = &qkv[(t * 8 + m) * 768 + 256 + h * 128];
        float a0 = 0.f, a1 = 0.f, a2 = 0.f, a3 = 0.f;
        #pragma unroll 8
        for (int d = 0; d < 128; d += 4) {
            a0 = fmaf(q[d],     kk[d],     a0);
            a1 = fmaf(q[d + 1], kk[d + 1], a1);
            a2 = fmaf(q[d + 2], kk[d + 2], a2);
            a3 = fmaf(q[d + 3], kk[d + 3], a3);
        }
        float s = __fadd_rn(__fadd_rn(a0, a1), __fadd_rn(a2, a3));
        sc[((t * 2 + h) * 8 + l) * 8 + m] = s / 11.313708498984760f;
    }
    __syncthreads();

    // softmax over m: 32 rows (2 tokens x 2 heads x 8 l)
    if (tid < 32) {
        float* row = &sc[tid * 8];
        float mx = row[0];
        #pragma unroll
        for (int m = 1; m < 8; m++) mx = fmaxf(mx, row[m]);
        float e[8], sm = 0.f;
        #pragma unroll
        for (int m = 0; m < 8; m++) { e[m] = expf(row[m] - mx); sm += e[m]; }
        float inv = 1.f / sm;
        #pragma unroll
        for (int m = 0; m < 8; m++) row[m] = e[m] * inv;
    }
    __syncthreads();

    // o = a @ v -> aP (pair layout, 16 rows)
    {
        int e = tid, h = e >> 7;
        float sl[16];
        #pragma unroll
        for (int t = 0; t < 2; t++) {
            #pragma unroll
            for (int l = 0; l < 8; l++) {
                float s = 0.f;
                #pragma unroll
                for (int m = 0; m < 8; m++)
                    s = fmaf(sc[((t * 2 + h) * 8 + l) * 8 + m],
                             qkv[(t * 8 + m) * 768 + 512 + e], s);
                sl[t * 8 + l] = s;
            }
        }
        __syncthreads();   // aP reads (qkv GEMM) + qkv reads done
        #pragma unroll
        for (int p = 0; p < 8; p++)
            *(ull*)&aP[e * 16 + 2 * p] = pack2(sl[2 * p], sl[2 * p + 1]);
    }
    __syncthreads();

    // proj + residual (pair)
    {
        int col = tid;
        ull res[8];
        dot16kp((const ulonglong2*)aP, g_wT_out, 256, col, res);
        float bo = b_out[col];
        ull bop = pack2(bo, bo);
        #pragma unroll
        for (int p = 0; p < 8; p++) {
            ull old = *(ull*)&flatP[col * 16 + 2 * p];
            *(ull*)&flatP[col * 16 + 2 * p] = add2(add2(res[p], bop), old);
        }
    }
    __syncthreads();

    // LN2
    #pragma unroll
    for (int rr = w; rr < 16; rr += 8) {
        float v[8];
        float s = 0.f;
        #pragma unroll
        for (int k = 0; k < 8; k++) { v[k] = flatP[(lane + 32 * k) * 16 + rr]; s += v[k]; }
        s = warp_sum(s);
        float mu = s * (1.f / 256.f);
        float var = 0.f;
        #pragma unroll
        for (int k = 0; k < 8; k++) { float t = v[k] - mu; var = fmaf(t, t, var); }
        var = warp_sum(var);
        float rs = 1.0f / sqrtf(var * (1.f / 256.f) + 1e-5f);
        #pragma unroll
        for (int k = 0; k < 8; k++) {
            int d = lane + 32 * k;
            aP[d * 16 + rr] = (v[k] - mu) * rs * ln2_g[d] + ln2_b[d];
        }
    }
    __syncthreads();

    // ffn1 + gelu -> hP (pair; aliases qkv, which is dead now)
    {
        int col = tid;
        ull res[8];
        dot16kp((const ulonglong2*)aP, g_wT_f1, 256, col, res);
        float b1 = fb1[col];
        #pragma unroll
        for (int p = 0; p < 8; p++) {
            float lo, hi; unpack2(lo, hi, res[p]);
            float u0 = __fadd_rn(lo, b1), u1 = __fadd_rn(hi, b1);
            float g0 = 0.5f * u0 * (1.0f + erff(u0 * 0.70710678118654752f));
            float g1 = 0.5f * u1 * (1.0f + erff(u1 * 0.70710678118654752f));
            *(ull*)&hP[col * 16 + 2 * p] = pack2(g0, g1);
        }
    }
    __syncthreads();

    // ffn2 + residual (pair)
    {
        int col = tid;
        ull res[8];
        dot16kp((const ulonglong2*)hP, g_wT_f2, 256, col, res);
        float b2 = fb2[col];
        ull b2p = pack2(b2, b2);
        #pragma unroll
        for (int p = 0; p < 8; p++) {
            ull old = *(ull*)&flatP[col * 16 + 2 * p];
            *(ull*)&flatP[col * 16 + 2 * p] = add2(add2(res[p], b2p), old);
        }
    }
    __syncthreads();

    // dec -> flatten (global, row-major (c,i))
    {
        int col = tid;
        ull res[8];
        dot16kp((const ulonglong2*)flatP, g_wT_dec, 256, col, res);
        float bd = db[col];
        #pragma unroll
        for (int p = 0; p < 8; p++) {
            float lo, hi; unpack2(lo, hi, res[p]);
            int gi = i0 + (p >> 2);
            int c0 = (2 * p) & 7, c1 = (2 * p + 1) & 7;
            out_flat[((size_t)c0 * BB + gi) * 256 + col] = __fadd_rn(lo, bd);
            out_flat[((size_t)c1 * BB + gi) * 256 + col] = __fadd_rn(hi, bd);
        }
    }
}

// ---------------------------------------------------------------- knorm ------
__global__ void __launch_bounds__(256) knorm_kernel(const float* __restrict__ keys) {
    int gw = (blockIdx.x * 256 + threadIdx.x) >> 5;
    int lane = threadIdx.x & 31;
    if (gw >= CB * PP) return;
    const float* row = keys + (size_t)gw * 256;
    double s = 0.0;
    #pragma unroll
    for (int k = 0; k < 8; k++) {
        double t = (double)row[lane + 32 * k];
        s = fma(t, t, s);
    }
    s = warp_sum_d(s);
    if (lane == 0) g_knorm[gw] = (float)s;
}

// ---------------------------------------------------------------- Kernel B ---
// Fused distance GEMM (packed f32x2, 8 row-pairs) + 2-way j blocking + top-8.
__global__ void __launch_bounds__(256) dist_kernel(const float* __restrict__ flat)
{
    __shared__ __align__(16) float Fp[256 * 16];   // pair layout [d][8 pairs]
    __shared__ float S[16][517];
    __shared__ float mv[16][128];
    __shared__ unsigned short mi[16][128];

    int c = blockIdx.y, ib = blockIdx.x, tid = threadIdx.x;
    int i0 = ib * 16;
    int r = tid & 15, sub = tid >> 4;

    for (int idx = tid; idx < 1024; idx += 256) {
        int rr = idx >> 6, d4 = idx & 63;
        float4 v = *(const float4*)(flat + ((size_t)c * BB + i0 + rr) * 256 + d4 * 4);
        int off = (rr >> 1) * 2 + (rr & 1);
        Fp[(4 * d4 + 0) * 16 + off] = v.x;
        Fp[(4 * d4 + 1) * 16 + off] = v.y;
        Fp[(4 * d4 + 2) * 16 + off] = v.z;
        Fp[(4 * d4 + 3) * 16 + off] = v.w;
    }
    __syncthreads();

    float tv[NSHORT];
    int   ti[NSHORT];
    #pragma unroll
    for (int t = 0; t < NSHORT; ++t) { tv[t] = -1e30f; ti[t] = 0; }

    const ulonglong2* Fp2 = (const ulonglong2*)Fp;   // 4 per d

    for (int tile = 0; tile < 4; ++tile) {
        int j = tile * 512 + tid;
        const float4* kp = g_kT + (size_t)c * 64 * PP + j;
        ull acc0[8], acc1[8];
        #pragma unroll
        for (int p = 0; p < 8; ++p) { acc0[p] = 0ULL; acc1[p] = 0ULL; }
        #pragma unroll 2
        for (int d4 = 0; d4 < 64; ++d4) {
            float4 ka = __ldg(kp + (size_t)d4 * PP);
            float4 kb = __ldg(kp + (size_t)d4 * PP + 256);
            #pragma unroll
            for (int e = 0; e < 4; ++e) {
                int d = 4 * d4 + e;
                float kae = (&ka.x)[e], kbe = (&kb.x)[e];
                ull ka2 = pack2(kae, kae);
                ull kb2 = pack2(kbe, kbe);
                ulonglong2 f01 = Fp2[d * 4 + 0];
                ulonglong2 f23 = Fp2[d * 4 + 1];
                ulonglong2 f45 = Fp2[d * 4 + 2];
                ulonglong2 f67 = Fp2[d * 4 + 3];
                acc0[0] = fma2(f01.x, ka2, acc0[0]); acc0[1] = fma2(f01.y, ka2, acc0[1]);
                acc0[2] = fma2(f23.x, ka2, acc0[2]); acc0[3] = fma2(f23.y, ka2, acc0[3]);
                acc0[4] = fma2(f45.x, ka2, acc0[4]); acc0[5] = fma2(f45.y, ka2, acc0[5]);
                acc0[6] = fma2(f67.x, ka2, acc0[6]); acc0[7] = fma2(f67.y, ka2, acc0[7]);
                acc1[0] = fma2(f01.x, kb2, acc1[0]); acc1[1] = fma2(f01.y, kb2, acc1[1]);
                acc1[2] = fma2(f23.x, kb2, acc1[2]); acc1[3] = fma2(f23.y, kb2, acc1[3]);
                acc1[4] = fma2(f45.x, kb2, acc1[4]); acc1[5] = fma2(f45.y, kb2, acc1[5]);
                acc1[6] = fma2(f67.x, kb2, acc1[6]); acc1[7] = fma2(f67.y, kb2, acc1[7]);
            }
        }
        float kn0 = g_knorm[c * PP + j];
        float kn1 = g_knorm[c * PP + j + 256];
        #pragma unroll
        for (int p = 0; p < 8; ++p) {
            float a, b2v;
            unpack2(a, b2v, acc0[p]);
            S[2 * p][tid]     = fmaf(2.f, a,   -kn0);
            S[2 * p + 1][tid] = fmaf(2.f, b2v, -kn0);
            unpack2(a, b2v, acc1[p]);
            S[2 * p][tid + 256]     = fmaf(2.f, a,   -kn1);
            S[2 * p + 1][tid + 256] = fmaf(2.f, b2v, -kn1);
        }
        __syncthreads();
        // per-row top-8 scan: thread (r,sub) scans 32 ascending columns
        #pragma unroll 4
        for (int q = 0; q < 32; ++q) {
            int col = sub * 32 + q;
            float v = S[r][col];
            int jj = tile * 512 + col;
            if (v > tv[NSHORT - 1]) {
                tv[NSHORT - 1] = v; ti[NSHORT - 1] = jj;
                #pragma unroll
                for (int p = NSHORT - 1; p > 0; --p) {
                    if (tv[p] > tv[p - 1] || (tv[p] == tv[p - 1] && ti[p] < ti[p - 1])) {
                        float a = tv[p]; tv[p] = tv[p - 1]; tv[p - 1] = a;
                        int   b = ti[p]; ti[p] = ti[p - 1]; ti[p - 1] = b;
                    }
                }
            }
        }
        __syncthreads();
    }

    // merge 16 per-thread lists per row
    #pragma unroll
    for (int t = 0; t < NSHORT; ++t) {
        mv[r][sub * 8 + t] = tv[t];
        mi[r][sub * 8 + t] = (unsigned short)ti[t];
    }
    __syncthreads();

    if (tid < 16) {
        int row = tid;
        float fv[NSHORT];
        int   fi[NSHORT];
        #pragma unroll
        for (int t = 0; t < NSHORT; ++t) { fv[t] = -1e30f; fi[t] = 0; }
        for (int e = 0; e < 128; ++e) {
            float v = mv[row][e];
            int jj = (int)mi[row][e];
            if (v > fv[NSHORT - 1] || (v == fv[NSHORT - 1] && jj < fi[NSHORT - 1])) {
                fv[NSHORT - 1] = v; fi[NSHORT - 1] = jj;
                #pragma unroll
                for (int p = NSHORT - 1; p > 0; --p) {
                    if (fv[p] > fv[p - 1] || (fv[p] == fv[p - 1] && fi[p] < fi[p - 1])) {
                        float a = fv[p]; fv[p] = fv[p - 1]; fv[p - 1] = a;
                        int   b = fi[p]; fi[p] = fi[p - 1]; fi[p - 1] = b;
                    }
                }
            }
        }
        int ig = i0 + row;
        #pragma unroll
        for (int t = 0; t < NSHORT; ++t)
            g_short[((size_t)ig * 8 + c) * NSHORT + t] = fi[t];
    }
}

// ------------------------------------------------------- refine + gather ----
// fp64 exact dot + pre-rounded C32 from knorm; fp32 tensor-boundary emulation
// of the reference dist, tie-break by lower index (jax.lax.top_k). After
// selection the whole warp gathers the 4 chosen qk/qv rows (fused gather).
__global__ void __launch_bounds__(256) refine_kernel(
    const float* __restrict__ flat, const float* __restrict__ keys,
    const float* __restrict__ values, const float* __restrict__ counter,
    float* __restrict__ out)
{
    int gw = (blockIdx.x * 256 + threadIdx.x) >> 5;   // row = i*8 + c
    int lane = threadIdx.x & 31;
    if (gw >= BB * CB) return;
    int i = gw >> 3, c = gw & 7;

    const float* frow = flat + ((size_t)c * BB + i) * 256;
    double f[8];
    double fn = 0.0;
    #pragma unroll
    for (int k = 0; k < 8; k++) {
        f[k] = (double)frow[lane + 32 * k];
        fn += f[k] * f[k];
    }
    fn = warp_sum_d(fn);

    float sv[NSHORT];
    int   si[NSHORT];
    float A32 = (float)fn;
    #pragma unroll
    for (int t = 0; t < NSHORT; ++t) {
        int idx = g_short[(size_t)gw * NSHORT + t];
        si[t] = idx;
        const float* krow = keys + ((size_t)c * PP + idx) * 256;
        double dot = 0.0;
        #pragma unroll
        for (int k = 0; k < 8; k++)
            dot = fma(f[k], (double)krow[lane + 32 * k], dot);
        dot = warp_sum_d(dot);
        float B32 = 2.0f * (float)dot;
        float C32 = __ldg(g_knorm + c * PP + idx);
        float t1  = __fadd_rn(A32, -B32);
        float t2  = __fadd_rn(t1, C32);
        sv[t] = -t2;
    }

    if (lane == 0) {
        #pragma unroll
        for (int a = 0; a < TK; ++a) {
            int best = a;
            #pragma unroll
            for (int b2 = a + 1; b2 < NSHORT; ++b2) {
                if (sv[b2] > sv[best] || (sv[b2] == sv[best] && si[b2] < si[best]))
                    best = b2;
            }
            float vtmp = sv[a]; sv[a] = sv[best]; sv[best] = vtmp;
            int   itmp = si[a]; si[a] = si[best]; si[best] = itmp;
            size_t o = ((size_t)gw) * 4 + a;
            out[OFF_IND + o]  = (float)si[a];
            out[OFF_DIST + o] = sv[a];
            out[OFF_CNT + o]  = counter[c * PP + si[a]];
        }
    }

    // fused gather: broadcast selected indices, warp copies qk/qv rows
    #pragma unroll
    for (int a = 0; a < TK; ++a) {
        int idx = __shfl_sync(0xffffffffu, si[a], 0);
        size_t grow = (size_t)gw * 4 + a;          // output row index
        const float4* ks = (const float4*)(keys   + ((size_t)c * PP + idx) * 256);
        const float4* vs = (const float4*)(values + ((size_t)c * PP + idx) * 256);
        float4* oqk = (float4*)(out + OFF_QK) + grow * 64;
        float4* oqv = (float4*)(out + OFF_QV) + grow * 64;
        oqv[lane]      = vs[lane];
        oqv[lane + 32] = vs[lane + 32];
        oqk[lane]      = ks[lane];
        oqk[lane + 32] = ks[lane + 32];
    }
}

// -----------------------------------------------------------------------------
#define ENC_SMEM 82944

extern "C" void kernel_launch(void* const* d_in, const int* in_sizes, int n_in,
                              void* d_out, int out_size) {
    const float* x       = (const float*)d_in[0];
    const float* keys    = (const float*)d_in[1];
    const float* values  = (const float*)d_in[2];
    const float* counter = (const float*)d_in[3];
    const float* ln1_g   = (const float*)d_in[4];
    const float* ln1_b   = (const float*)d_in[5];
    const float* w_in    = (const float*)d_in[6];
    const float* b_in    = (const float*)d_in[7];
    const float* w_out   = (const float*)d_in[8];
    const float* b_out   = (const float*)d_in[9];
    const float* ln2_g   = (const float*)d_in[10];
    const float* ln2_b   = (const float*)d_in[11];
    const float* fw1     = (const float*)d_in[12];
    const float* fb1     = (const float*)d_in[13];
    const float* fw2     = (const float*)d_in[14];
    const float* fb2     = (const float*)d_in[15];
    const float* dw      = (const float*)d_in[16];
    const float* db      = (const float*)d_in[17];
    float* out = (float*)d_out;

    cudaFuncSetAttribute(enc_kernel,
                         cudaFuncAttributeMaxDynamicSharedMemorySize, ENC_SMEM);

    transW_kernel<<<448, 256>>>(w_in, w_out, fw1, fw2, dw);

    enc_kernel<<<BB / 2, 256, ENC_SMEM>>>(x, ln1_g, ln1_b, b_in, b_out,
                                          ln2_g, ln2_b, fb1, fb2, db,
                                          out + OFF_FLAT);

    transK_kernel<<<CB * 64 * PP / 256, 256>>>(keys);
    knorm_kernel<<<2048, 256>>>(keys);

    dist_kernel<<<dim3(BB / 16, CB), 256>>>(out + OFF_FLAT);
    refine_kernel<<<BB * CB / 8, 256>>>(out + OFF_FLAT, keys, values, counter, out);
}

// round 17
// speedup vs baseline: 2.1275x; 1.1459x over previous
#include <cuda_runtime.h>
#include <math.h>
#include <stdint.h>

#define CB   8
#define PP   2048
#define DKx  256
#define BB   8192
#define TK   4

// output offsets (elements, fp32)
#define OFF_QV   0ULL
#define OFF_QK   67108864ULL
#define OFF_IND  134217728ULL
#define OFF_DIST 134479872ULL
#define OFF_CNT  134742016ULL
#define OFF_FLAT 135004160ULL

#define NSHORT 8

typedef unsigned long long ull;

__device__ int    g_short[BB * CB * NSHORT];
__device__ float  g_knorm[CB * PP];     // fp64-accumulated, fp32-rounded |k|^2
// transposed keys: coalesced float4 over contraction dim [(c*64 + d4)*2048 + j]
__device__ float4 g_kT[CB * 64 * PP];
// transposed weights for enc (coalesced float4 over contraction dim)
__device__ float4 g_wT_in[64 * 768];       // [d4*768 + col]
__device__ float4 g_wT_out[64 * 256];
__device__ float4 g_wT_f1[64 * 256];
__device__ float4 g_wT_f2[64 * 256];
__device__ float4 g_wT_dec[64 * 256];

// --------------------------------------------------------- packed f32x2 ----
__device__ __forceinline__ ull pack2(float lo, float hi) {
    ull r; asm("mov.b64 %0,{%1,%2};" : "=l"(r) : "f"(lo), "f"(hi)); return r;
}
__device__ __forceinline__ void unpack2(float& lo, float& hi, ull v) {
    asm("mov.b64 {%0,%1},%2;" : "=f"(lo), "=f"(hi) : "l"(v));
}
__device__ __forceinline__ ull fma2(ull a, ull b, ull c) {
    ull d; asm("fma.rn.f32x2 %0,%1,%2,%3;" : "=l"(d) : "l"(a), "l"(b), "l"(c)); return d;
}
__device__ __forceinline__ ull add2(ull a, ull b) {
    ull d; asm("add.rn.f32x2 %0,%1,%2;" : "=l"(d) : "l"(a), "l"(b)); return d;
}
__device__ __forceinline__ ull mul2(ull a, ull b) {
    ull d; asm("mul.rn.f32x2 %0,%1,%2;" : "=l"(d) : "l"(a), "l"(b)); return d;
}
// Kahan on packed pairs; fma2(x,-1,y) rounds identically to sub(y,x).
__device__ __forceinline__ void kadd2(ull& s, ull& c, ull v) {
    const ull neg1 = 0xBF800000BF800000ULL;
    ull y = fma2(c, neg1, v);
    ull t = add2(s, y);
    c = fma2(y, neg1, fma2(s, neg1, t));
    s = t;
}

__device__ __forceinline__ float warp_sum(float v) {
    #pragma unroll
    for (int o = 16; o; o >>= 1) v += __shfl_xor_sync(0xffffffffu, v, o);
    return v;
}
__device__ __forceinline__ double warp_sum_d(double v) {
    #pragma unroll
    for (int o = 16; o; o >>= 1) v += __shfl_xor_sync(0xffffffffu, v, o);
    return v;
}

// Knuth TwoSum: s += b exactly, rounding error accumulated into e.
__device__ __forceinline__ void twosum(float& s, float& e, float b) {
    float t  = __fadd_rn(s, b);
    float z  = __fsub_rn(t, s);
    float e2 = __fadd_rn(__fsub_rn(s, __fsub_rn(t, z)), __fsub_rn(b, z));
    e = __fadd_rn(e, e2);
    s = t;
}

// ------------------------------------------------------------- transposes ---
// merged: blocks [0,192)=w_in, [192,256)=w_out, [256,320)=fw1,
// [320,384)=fw2, [384,448)=dw
__global__ void __launch_bounds__(256) transW_kernel(
    const float* __restrict__ w_in,  const float* __restrict__ w_out,
    const float* __restrict__ fw1,   const float* __restrict__ fw2,
    const float* __restrict__ dw) {
    int b = blockIdx.x;
    const float* src; float4* dst; int NC; int base;
    if (b < 192)      { src = w_in;  dst = g_wT_in;  NC = 768; base = b; }
    else if (b < 256) { src = w_out; dst = g_wT_out; NC = 256; base = b - 192; }
    else if (b < 320) { src = fw1;   dst = g_wT_f1;  NC = 256; base = b - 256; }
    else if (b < 384) { src = fw2;   dst = g_wT_f2;  NC = 256; base = b - 320; }
    else              { src = dw;    dst = g_wT_dec; NC = 256; base = b - 384; }
    int idx = base * 256 + threadIdx.x;
    if (idx >= 64 * NC) return;
    int d4 = idx / NC, col = idx % NC;
    const float* p = src + (size_t)col * 256 + 4 * d4;
    dst[idx] = make_float4(p[0], p[1], p[2], p[3]);
}

__global__ void __launch_bounds__(256) transK_kernel(const float* __restrict__ keys) {
    int idx = blockIdx.x * 256 + threadIdx.x;           // ((c*64+d4)*2048 + j)
    int j = idx & 2047, rest = idx >> 11;
    int d4 = rest & 63, c = rest >> 6;
    const float* p = keys + ((size_t)(c * PP + j)) * 256 + 4 * d4;
    g_kT[idx] = make_float4(p[0], p[1], p[2], p[3]);
}

// Packed compensated dot over 16 rows (8 pairs): 32-MAC serial chunks; two
// chunks joined with add2, kadd2 every second chunk (Kahan chain preserved).
__device__ __forceinline__ void dot16kp(const ulonglong2* __restrict__ Ap,
                                        const float4* __restrict__ wT4, int NC, int col,
                                        ull* out) {
    ull s[8], c[8], half[8];
    #pragma unroll
    for (int p = 0; p < 8; p++) { s[p] = 0ULL; c[p] = 0ULL; }
    #pragma unroll 2
    for (int g = 0; g < 8; ++g) {
        float4 w[8];
        #pragma unroll
        for (int q = 0; q < 8; ++q)
            w[q] = __ldg(wT4 + (size_t)(8 * g + q) * NC + col);
        ull ch[8];
        {
            ull wp = pack2(w[0].x, w[0].x);
            ulonglong2 a01 = Ap[(g * 32) * 4 + 0];
            ulonglong2 a23 = Ap[(g * 32) * 4 + 1];
            ulonglong2 a45 = Ap[(g * 32) * 4 + 2];
            ulonglong2 a67 = Ap[(g * 32) * 4 + 3];
            ch[0] = mul2(a01.x, wp); ch[1] = mul2(a01.y, wp);
            ch[2] = mul2(a23.x, wp); ch[3] = mul2(a23.y, wp);
            ch[4] = mul2(a45.x, wp); ch[5] = mul2(a45.y, wp);
            ch[6] = mul2(a67.x, wp); ch[7] = mul2(a67.y, wp);
        }
        #pragma unroll
        for (int dd = 1; dd < 32; ++dd) {
            float we = (&w[dd >> 2].x)[dd & 3];
            ull wp = pack2(we, we);
            int d = g * 32 + dd;
            ulonglong2 a01 = Ap[d * 4 + 0];
            ulonglong2 a23 = Ap[d * 4 + 1];
            ulonglong2 a45 = Ap[d * 4 + 2];
            ulonglong2 a67 = Ap[d * 4 + 3];
            ch[0] = fma2(a01.x, wp, ch[0]); ch[1] = fma2(a01.y, wp, ch[1]);
            ch[2] = fma2(a23.x, wp, ch[2]); ch[3] = fma2(a23.y, wp, ch[3]);
            ch[4] = fma2(a45.x, wp, ch[4]); ch[5] = fma2(a45.y, wp, ch[5]);
            ch[6] = fma2(a67.x, wp, ch[6]); ch[7] = fma2(a67.y, wp, ch[7]);
        }
        if ((g & 1) == 0) {
            #pragma unroll
            for (int p = 0; p < 8; p++) half[p] = ch[p];
        } else {
            #pragma unroll
            for (int p = 0; p < 8; p++) kadd2(s[p], c[p], add2(half[p], ch[p]));
        }
    }
    #pragma unroll
    for (int p = 0; p < 8; p++) out[p] = add2(s[p], c[p]);
}

// ---------------------------------------------------------------- Kernel A ---
// 2 tokens per CTA: 16 residual rows, pair layout buf[d*16 + row].
__global__ void __launch_bounds__(256, 2) enc_kernel(
    const float* __restrict__ x,
    const float* __restrict__ ln1_g, const float* __restrict__ ln1_b,
    const float* __restrict__ b_in,  const float* __restrict__ b_out,
    const float* __restrict__ ln2_g, const float* __restrict__ ln2_b,
    const float* __restrict__ fb1,   const float* __restrict__ fb2,
    const float* __restrict__ db,
    float* __restrict__ out_flat)
{
    extern __shared__ __align__(16) float smem_dyn[];
    float* flatP = smem_dyn;                 // 4096 floats
    float* aP    = smem_dyn + 4096;          // 4096 floats
    float* qkv   = smem_dyn + 8192;          // 12288 floats [16][768]
    float* sc    = smem_dyn + 20480;         // 256 floats [2][2][8][8]
    float* hP    = qkv;                      // ffn hidden (pair), aliases qkv

    int i0 = blockIdx.x * 2, tid = threadIdx.x;
    int w = tid >> 5, lane = tid & 31;

    // stage x (2 tokens) into pair layout: off == row
    for (int idx = tid; idx < 1024; idx += 256) {
        int l = idx >> 6, d4 = idx & 63;          // l = row 0..15
        int gi = i0 + (l >> 3);
        float4 v = *(const float4*)(x + ((size_t)gi * 8 + (l & 7)) * 256 + 4 * d4);
        flatP[(4 * d4 + 0) * 16 + l] = v.x;
        flatP[(4 * d4 + 1) * 16 + l] = v.y;
        flatP[(4 * d4 + 2) * 16 + l] = v.z;
        flatP[(4 * d4 + 3) * 16 + l] = v.w;
    }
    __syncthreads();

    // LN1: each warp handles rows w and w+8
    #pragma unroll
    for (int rr = w; rr < 16; rr += 8) {
        float v[8];
        float s = 0.f;
        #pragma unroll
        for (int k = 0; k < 8; k++) { v[k] = flatP[(lane + 32 * k) * 16 + rr]; s += v[k]; }
        s = warp_sum(s);
        float mu = s * (1.f / 256.f);
        float var = 0.f;
        #pragma unroll
        for (int k = 0; k < 8; k++) { float t = v[k] - mu; var = fmaf(t, t, var); }
        var = warp_sum(var);
        float rs = 1.0f / sqrtf(var * (1.f / 256.f) + 1e-5f);
        #pragma unroll
        for (int k = 0; k < 8; k++) {
            int d = lane + 32 * k;
            aP[d * 16 + rr] = (v[k] - mu) * rs * ln1_g[d] + ln1_b[d];
        }
    }
    __syncthreads();

    // qkv = h0 @ w_in^T + b_in  (row-major out for attention)
    for (int ch = 0; ch < 3; ++ch) {
        int col = ch * 256 + tid;
        ull res[8];
        dot16kp((const ulonglong2*)aP, g_wT_in, 768, col, res);
        float bi = b_in[col];
        #pragma unroll
        for (int p = 0; p < 8; p++) {
            float lo, hi; unpack2(lo, hi, res[p]);
            qkv[(2 * p) * 768 + col]     = __fadd_rn(lo, bi);
            qkv[(2 * p + 1) * 768 + col] = __fadd_rn(hi, bi);
        }
    }
    __syncthreads();

    // scores: 2 tokens x 2 heads x 64 (l,m) = 256 threads
    {
        int t = tid >> 7, h = (tid >> 6) & 1, rem = tid & 63, l = rem >> 3, m = rem & 7;
        const float* q  = &qkv[(t * 8 + l) * 768 + h * 128];
        const float* kk = &qkv[(t * 8 + m) * 768 + 256 + h * 128];
        float a0 = 0.f, a1 = 0.f, a2 = 0.f, a3 = 0.f;
        #pragma unroll 8
        for (int d = 0; d < 128; d += 4) {
            a0 = fmaf(q[d],     kk[d],     a0);
            a1 = fmaf(q[d + 1], kk[d + 1], a1);
            a2 = fmaf(q[d + 2], kk[d + 2], a2);
            a3 = fmaf(q[d + 3], kk[d + 3], a3);
        }
        float s = __fadd_rn(__fadd_rn(a0, a1), __fadd_rn(a2, a3));
        sc[((t * 2 + h) * 8 + l) * 8 + m] = s / 11.313708498984760f;
    }
    __syncthreads();

    // softmax over m: 32 rows (2 tokens x 2 heads x 8 l)
    if (tid < 32) {
        float* row = &sc[tid * 8];
        float mx = row[0];
        #pragma unroll
        for (int m = 1; m < 8; m++) mx = fmaxf(mx, row[m]);
        float e[8], sm = 0.f;
        #pragma unroll
        for (int m = 0; m < 8; m++) { e[m] = expf(row[m] - mx); sm += e[m]; }
        float inv = 1.f / sm;
        #pragma unroll
        for (int m = 0; m < 8; m++) row[m] = e[m] * inv;
    }
    __syncthreads();

    // o = a @ v -> aP (pair layout, 16 rows)
    {
        int e = tid, h = e >> 7;
        float sl[16];
        #pragma unroll
        for (int t = 0; t < 2; t++) {
            #pragma unroll
            for (int l = 0; l < 8; l++) {
                float s = 0.f;
                #pragma unroll
                for (int m = 0; m < 8; m++)
                    s = fmaf(sc[((t * 2 + h) * 8 + l) * 8 + m],
                             qkv[(t * 8 + m) * 768 + 512 + e], s);
                sl[t * 8 + l] = s;
            }
        }
        __syncthreads();   // aP reads (qkv GEMM) + qkv reads done
        #pragma unroll
        for (int p = 0; p < 8; p++)
            *(ull*)&aP[e * 16 + 2 * p] = pack2(sl[2 * p], sl[2 * p + 1]);
    }
    __syncthreads();

    // proj + residual (pair)
    {
        int col = tid;
        ull res[8];
        dot16kp((const ulonglong2*)aP, g_wT_out, 256, col, res);
        float bo = b_out[col];
        ull bop = pack2(bo, bo);
        #pragma unroll
        for (int p = 0; p < 8; p++) {
            ull old = *(ull*)&flatP[col * 16 + 2 * p];
            *(ull*)&flatP[col * 16 + 2 * p] = add2(add2(res[p], bop), old);
        }
    }
    __syncthreads();

    // LN2
    #pragma unroll
    for (int rr = w; rr < 16; rr += 8) {
        float v[8];
        float s = 0.f;
        #pragma unroll
        for (int k = 0; k < 8; k++) { v[k] = flatP[(lane + 32 * k) * 16 + rr]; s += v[k]; }
        s = warp_sum(s);
        float mu = s * (1.f / 256.f);
        float var = 0.f;
        #pragma unroll
        for (int k = 0; k < 8; k++) { float t = v[k] - mu; var = fmaf(t, t, var); }
        var = warp_sum(var);
        float rs = 1.0f / sqrtf(var * (1.f / 256.f) + 1e-5f);
        #pragma unroll
        for (int k = 0; k < 8; k++) {
            int d = lane + 32 * k;
            aP[d * 16 + rr] = (v[k] - mu) * rs * ln2_g[d] + ln2_b[d];
        }
    }
    __syncthreads();

    // ffn1 + gelu -> hP (pair; aliases qkv, which is dead now)
    {
        int col = tid;
        ull res[8];
        dot16kp((const ulonglong2*)aP, g_wT_f1, 256, col, res);
        float b1 = fb1[col];
        #pragma unroll
        for (int p = 0; p < 8; p++) {
            float lo, hi; unpack2(lo, hi, res[p]);
            float u0 = __fadd_rn(lo, b1), u1 = __fadd_rn(hi, b1);
            float g0 = 0.5f * u0 * (1.0f + erff(u0 * 0.70710678118654752f));
            float g1 = 0.5f * u1 * (1.0f + erff(u1 * 0.70710678118654752f));
            *(ull*)&hP[col * 16 + 2 * p] = pack2(g0, g1);
        }
    }
    __syncthreads();

    // ffn2 + residual (pair)
    {
        int col = tid;
        ull res[8];
        dot16kp((const ulonglong2*)hP, g_wT_f2, 256, col, res);
        float b2 = fb2[col];
        ull b2p = pack2(b2, b2);
        #pragma unroll
        for (int p = 0; p < 8; p++) {
            ull old = *(ull*)&flatP[col * 16 + 2 * p];
            *(ull*)&flatP[col * 16 + 2 * p] = add2(add2(res[p], b2p), old);
        }
    }
    __syncthreads();

    // dec -> flatten (global, row-major (c,i))
    {
        int col = tid;
        ull res[8];
        dot16kp((const ulonglong2*)flatP, g_wT_dec, 256, col, res);
        float bd = db[col];
        #pragma unroll
        for (int p = 0; p < 8; p++) {
            float lo, hi; unpack2(lo, hi, res[p]);
            int gi = i0 + (p >> 2);
            int c0 = (2 * p) & 7, c1 = (2 * p + 1) & 7;
            out_flat[((size_t)c0 * BB + gi) * 256 + col] = __fadd_rn(lo, bd);
            out_flat[((size_t)c1 * BB + gi) * 256 + col] = __fadd_rn(hi, bd);
        }
    }
}

// ---------------------------------------------------------------- knorm ------
__global__ void __launch_bounds__(256) knorm_kernel(const float* __restrict__ keys) {
    int gw = (blockIdx.x * 256 + threadIdx.x) >> 5;
    int lane = threadIdx.x & 31;
    if (gw >= CB * PP) return;
    const float* row = keys + (size_t)gw * 256;
    double s = 0.0;
    #pragma unroll
    for (int k = 0; k < 8; k++) {
        double t = (double)row[lane + 32 * k];
        s = fma(t, t, s);
    }
    s = warp_sum_d(s);
    if (lane == 0) g_knorm[gw] = (float)s;
}

// ---------------------------------------------------------------- Kernel B ---
// Fused distance GEMM (packed f32x2, 8 row-pairs) + 2-way j blocking + top-8.
__global__ void __launch_bounds__(256) dist_kernel(const float* __restrict__ flat)
{
    __shared__ __align__(16) float Fp[256 * 16];   // pair layout [d][8 pairs]
    __shared__ float S[16][517];
    __shared__ float mv[16][128];
    __shared__ unsigned short mi[16][128];

    int c = blockIdx.y, ib = blockIdx.x, tid = threadIdx.x;
    int i0 = ib * 16;
    int r = tid & 15, sub = tid >> 4;

    for (int idx = tid; idx < 1024; idx += 256) {
        int rr = idx >> 6, d4 = idx & 63;
        float4 v = *(const float4*)(flat + ((size_t)c * BB + i0 + rr) * 256 + d4 * 4);
        int off = (rr >> 1) * 2 + (rr & 1);
        Fp[(4 * d4 + 0) * 16 + off] = v.x;
        Fp[(4 * d4 + 1) * 16 + off] = v.y;
        Fp[(4 * d4 + 2) * 16 + off] = v.z;
        Fp[(4 * d4 + 3) * 16 + off] = v.w;
    }
    __syncthreads();

    float tv[NSHORT];
    int   ti[NSHORT];
    #pragma unroll
    for (int t = 0; t < NSHORT; ++t) { tv[t] = -1e30f; ti[t] = 0; }

    const ulonglong2* Fp2 = (const ulonglong2*)Fp;   // 4 per d

    for (int tile = 0; tile < 4; ++tile) {
        int j = tile * 512 + tid;
        const float4* kp = g_kT + (size_t)c * 64 * PP + j;
        ull acc0[8], acc1[8];
        #pragma unroll
        for (int p = 0; p < 8; ++p) { acc0[p] = 0ULL; acc1[p] = 0ULL; }
        #pragma unroll 2
        for (int d4 = 0; d4 < 64; ++d4) {
            float4 ka = __ldg(kp + (size_t)d4 * PP);
            float4 kb = __ldg(kp + (size_t)d4 * PP + 256);
            #pragma unroll
            for (int e = 0; e < 4; ++e) {
                int d = 4 * d4 + e;
                float kae = (&ka.x)[e], kbe = (&kb.x)[e];
                ull ka2 = pack2(kae, kae);
                ull kb2 = pack2(kbe, kbe);
                ulonglong2 f01 = Fp2[d * 4 + 0];
                ulonglong2 f23 = Fp2[d * 4 + 1];
                ulonglong2 f45 = Fp2[d * 4 + 2];
                ulonglong2 f67 = Fp2[d * 4 + 3];
                acc0[0] = fma2(f01.x, ka2, acc0[0]); acc0[1] = fma2(f01.y, ka2, acc0[1]);
                acc0[2] = fma2(f23.x, ka2, acc0[2]); acc0[3] = fma2(f23.y, ka2, acc0[3]);
                acc0[4] = fma2(f45.x, ka2, acc0[4]); acc0[5] = fma2(f45.y, ka2, acc0[5]);
                acc0[6] = fma2(f67.x, ka2, acc0[6]); acc0[7] = fma2(f67.y, ka2, acc0[7]);
                acc1[0] = fma2(f01.x, kb2, acc1[0]); acc1[1] = fma2(f01.y, kb2, acc1[1]);
                acc1[2] = fma2(f23.x, kb2, acc1[2]); acc1[3] = fma2(f23.y, kb2, acc1[3]);
                acc1[4] = fma2(f45.x, kb2, acc1[4]); acc1[5] = fma2(f45.y, kb2, acc1[5]);
                acc1[6] = fma2(f67.x, kb2, acc1[6]); acc1[7] = fma2(f67.y, kb2, acc1[7]);
            }
        }
        float kn0 = g_knorm[c * PP + j];
        float kn1 = g_knorm[c * PP + j + 256];
        #pragma unroll
        for (int p = 0; p < 8; ++p) {
            float a, b2v;
            unpack2(a, b2v, acc0[p]);
            S[2 * p][tid]     = fmaf(2.f, a,   -kn0);
            S[2 * p + 1][tid] = fmaf(2.f, b2v, -kn0);
            unpack2(a, b2v, acc1[p]);
            S[2 * p][tid + 256]     = fmaf(2.f, a,   -kn1);
            S[2 * p + 1][tid + 256] = fmaf(2.f, b2v, -kn1);
        }
        __syncthreads();
        // per-row top-8 scan: thread (r,sub) scans 32 ascending columns
        #pragma unroll 4
        for (int q = 0; q < 32; ++q) {
            int col = sub * 32 + q;
            float v = S[r][col];
            int jj = tile * 512 + col;
            if (v > tv[NSHORT - 1]) {
                tv[NSHORT - 1] = v; ti[NSHORT - 1] = jj;
                #pragma unroll
                for (int p = NSHORT - 1; p > 0; --p) {
                    if (tv[p] > tv[p - 1] || (tv[p] == tv[p - 1] && ti[p] < ti[p - 1])) {
                        float a = tv[p]; tv[p] = tv[p - 1]; tv[p - 1] = a;
                        int   b = ti[p]; ti[p] = ti[p - 1]; ti[p - 1] = b;
                    }
                }
            }
        }
        __syncthreads();
    }

    // merge 16 per-thread lists per row
    #pragma unroll
    for (int t = 0; t < NSHORT; ++t) {
        mv[r][sub * 8 + t] = tv[t];
        mi[r][sub * 8 + t] = (unsigned short)ti[t];
    }
    __syncthreads();

    if (tid < 16) {
        int row = tid;
        float fv[NSHORT];
        int   fi[NSHORT];
        #pragma unroll
        for (int t = 0; t < NSHORT; ++t) { fv[t] = -1e30f; fi[t] = 0; }
        for (int e = 0; e < 128; ++e) {
            float v = mv[row][e];
            int jj = (int)mi[row][e];
            if (v > fv[NSHORT - 1] || (v == fv[NSHORT - 1] && jj < fi[NSHORT - 1])) {
                fv[NSHORT - 1] = v; fi[NSHORT - 1] = jj;
                #pragma unroll
                for (int p = NSHORT - 1; p > 0; --p) {
                    if (fv[p] > fv[p - 1] || (fv[p] == fv[p - 1] && fi[p] < fi[p - 1])) {
                        float a = fv[p]; fv[p] = fv[p - 1]; fv[p - 1] = a;
                        int   b = fi[p]; fi[p] = fi[p - 1]; fi[p - 1] = b;
                    }
                }
            }
        }
        int ig = i0 + row;
        #pragma unroll
        for (int t = 0; t < NSHORT; ++t)
            g_short[((size_t)ig * 8 + c) * NSHORT + t] = fi[t];
    }
}

// ------------------------------------------------------- refine + gather ----
// Compensated fp32 dot (TwoProduct + TwoSum, compensated shuffle reduce):
// abs error ~1e-10 << one dist32 ulp (3e-5). fn kept fp64 (single reduce).
// fp32 tensor-boundary emulation of reference dist, tie-break lower index.
// After selection the whole warp gathers the 4 chosen qk/qv rows.
__global__ void __launch_bounds__(256) refine_kernel(
    const float* __restrict__ flat, const float* __restrict__ keys,
    const float* __restrict__ values, const float* __restrict__ counter,
    float* __restrict__ out)
{
    int gw = (blockIdx.x * 256 + threadIdx.x) >> 5;   // row = i*8 + c
    int lane = threadIdx.x & 31;
    if (gw >= BB * CB) return;
    int i = gw >> 3, c = gw & 7;

    const float* frow = flat + ((size_t)c * BB + i) * 256;
    float fl[8];
    double fn = 0.0;
    #pragma unroll
    for (int k = 0; k < 8; k++) {
        fl[k] = frow[lane + 32 * k];
        double fd = (double)fl[k];
        fn = fma(fd, fd, fn);
    }
    fn = warp_sum_d(fn);

    float sv[NSHORT];
    int   si[NSHORT];
    float A32 = (float)fn;
    #pragma unroll
    for (int t = 0; t < NSHORT; ++t) {
        int idx = g_short[(size_t)gw * NSHORT + t];
        si[t] = idx;
        const float* krow = keys + ((size_t)c * PP + idx) * 256;
        // lane-local compensated dot
        float s = 0.f, e = 0.f;
        #pragma unroll
        for (int k = 0; k < 8; k++) {
            float kr = krow[lane + 32 * k];
            float p  = __fmul_rn(fl[k], kr);
            float pe = fmaf(fl[k], kr, -p);       // exact product error
            twosum(s, e, p);
            e = __fadd_rn(e, pe);
        }
        // compensated cross-lane reduction
        #pragma unroll
        for (int o = 16; o; o >>= 1) {
            float s2 = __shfl_xor_sync(0xffffffffu, s, o);
            float e2 = __shfl_xor_sync(0xffffffffu, e, o);
            e = __fadd_rn(e, e2);
            twosum(s, e, s2);
        }
        float dot32 = __fadd_rn(s, e);
        float B32 = 2.0f * dot32;
        float C32 = __ldg(g_knorm + c * PP + idx);
        float t1  = __fadd_rn(A32, -B32);
        float t2  = __fadd_rn(t1, C32);
        sv[t] = -t2;
    }

    if (lane == 0) {
        #pragma unroll
        for (int a = 0; a < TK; ++a) {
            int best = a;
            #pragma unroll
            for (int b2 = a + 1; b2 < NSHORT; ++b2) {
                if (sv[b2] > sv[best] || (sv[b2] == sv[best] && si[b2] < si[best]))
                    best = b2;
            }
            float vtmp = sv[a]; sv[a] = sv[best]; sv[best] = vtmp;
            int   itmp = si[a]; si[a] = si[best]; si[best] = itmp;
            size_t o = ((size_t)gw) * 4 + a;
            out[OFF_IND + o]  = (float)si[a];
            out[OFF_DIST + o] = sv[a];
            out[OFF_CNT + o]  = counter[c * PP + si[a]];
        }
    }

    // fused gather: broadcast selected indices, warp copies qk/qv rows
    #pragma unroll
    for (int a = 0; a < TK; ++a) {
        int idx = __shfl_sync(0xffffffffu, si[a], 0);
        size_t grow = (size_t)gw * 4 + a;          // output row index
        const float4* ks = (const float4*)(keys   + ((size_t)c * PP + idx) * 256);
        const float4* vs = (const float4*)(values + ((size_t)c * PP + idx) * 256);
        float4* oqk = (float4*)(out + OFF_QK) + grow * 64;
        float4* oqv = (float4*)(out + OFF_QV) + grow * 64;
        oqv[lane]      = vs[lane];
        oqv[lane + 32] = vs[lane + 32];
        oqk[lane]      = ks[lane];
        oqk[lane + 32] = ks[lane + 32];
    }
}

// -----------------------------------------------------------------------------
#define ENC_SMEM 82944

extern "C" void kernel_launch(void* const* d_in, const int* in_sizes, int n_in,
                              void* d_out, int out_size) {
    const float* x       = (const float*)d_in[0];
    const float* keys    = (const float*)d_in[1];
    const float* values  = (const float*)d_in[2];
    const float* counter = (const float*)d_in[3];
    const float* ln1_g   = (const float*)d_in[4];
    const float* ln1_b   = (const float*)d_in[5];
    const float* w_in    = (const float*)d_in[6];
    const float* b_in    = (const float*)d_in[7];
    const float* w_out   = (const float*)d_in[8];
    const float* b_out   = (const float*)d_in[9];
    const float* ln2_g   = (const float*)d_in[10];
    const float* ln2_b   = (const float*)d_in[11];
    const float* fw1     = (const float*)d_in[12];
    const float* fb1     = (const float*)d_in[13];
    const float* fw2     = (const float*)d_in[14];
    const float* fb2     = (const float*)d_in[15];
    const float* dw      = (const float*)d_in[16];
    const float* db      = (const float*)d_in[17];
    float* out = (float*)d_out;

    cudaFuncSetAttribute(enc_kernel,
                         cudaFuncAttributeMaxDynamicSharedMemorySize, ENC_SMEM);

    transW_kernel<<<448, 256>>>(w_in, w_out, fw1, fw2, dw);

    enc_kernel<<<BB / 2, 256, ENC_SMEM>>>(x, ln1_g, ln1_b, b_in, b_out,
                                          ln2_g, ln2_b, fb1, fb2, db,
                                          out + OFF_FLAT);

    transK_kernel<<<CB * 64 * PP / 256, 256>>>(keys);
    knorm_kernel<<<2048, 256>>>(keys);

    dist_kernel<<<dim3(BB / 16, CB), 256>>>(out + OFF_FLAT);
    refine_kernel<<<BB * CB / 8, 256>>>(out + OFF_FLAT, keys, values, counter, out);
}